// round 3
// baseline (speedup 1.0000x reference)
#include <cuda_runtime.h>
#include <cstdint>
#include <cstddef>

#define ENS       7
#define S_DIM     30
#define A_DIM     8
#define IN_DIM    38     // S_DIM + A_DIM
#define IN_PAD    40     // padded to multiple of CH
#define HID       200
#define OUT_DIM   31     // S_DIM + R_DIM
#define NHID      3      // hidden-to-hidden layers
#define TSAMP     128    // samples per CTA
#define NTHREADS  256    // 2 threads per sample (one per output-half)
#define CH        8      // weight rows per staged chunk
#define HALF_K    100    // output features per thread (HID/2)

// Shared memory plan (floats):
//   hsm : HID * TSAMP          = 25600   (activation columns, one per sample)
//   wbuf: 2 * CH * HID         =  3200   (double-buffered weight chunk)
// total = 28800 floats = 115200 bytes  -> 1 CTA / SM
#define SMEM_FLOATS (HID * TSAMP + 2 * CH * HID)
#define SMEM_BYTES  (SMEM_FLOATS * 4)

__device__ __forceinline__ void cp_async16(void* smem_dst, const void* gptr) {
    uint32_t saddr = (uint32_t)__cvta_generic_to_shared(smem_dst);
    asm volatile("cp.async.ca.shared.global [%0], [%1], 16;\n" :: "r"(saddr), "l"(gptr));
}
__device__ __forceinline__ void cp_commit() {
    asm volatile("cp.async.commit_group;\n");
}
__device__ __forceinline__ void cp_wait1() {
    asm volatile("cp.async.wait_group 1;\n" ::: "memory");
}
__device__ __forceinline__ void cp_wait0() {
    asm volatile("cp.async.wait_group 0;\n" ::: "memory");
}

__device__ __forceinline__ float swishf(float x) {
    // x * sigmoid(x)
    return __fdividef(x, 1.0f + __expf(-x));
}

__device__ __forceinline__ float softplusf(float z) {
    // numerically stable log(1 + exp(z))
    return fmaxf(z, 0.0f) + log1pf(__expf(-fabsf(z)));
}

// Stage one CH x HID weight chunk (rows c*CH .. c*CH+CH-1) into wdst via cp.async.
// Rows >= in_act (layer-1 padding) are zero-filled with plain STS.
__device__ __forceinline__ void load_chunk(float* wdst, const float* __restrict__ Wg,
                                           int c, int in_act) {
    const int SLOTS = CH * HID / 4;  // 400 float4 slots
    int slot = threadIdx.x;
#pragma unroll
    for (int r = 0; r < 2; ++r, slot += NTHREADS) {
        if (slot < SLOTS) {
            int row = slot / (HID / 4);
            int c4  = slot % (HID / 4);
            int j   = c * CH + row;
            float4* d4 = reinterpret_cast<float4*>(wdst) + slot;
            if (j < in_act) {
                const float4* src = reinterpret_cast<const float4*>(Wg)
                                    + (size_t)j * (HID / 4) + c4;
                cp_async16(d4, src);
            } else {
                *d4 = make_float4(0.f, 0.f, 0.f, 0.f);
            }
        }
    }
}

// One dense layer (in_act inputs -> HID outputs), this thread computing its
// half (HALF_K features). Result (pre-bias) accumulated into acc[]; bias added
// at the end directly from global (broadcast LDG, avoids a smem race window).
__device__ __forceinline__ void dense_layer(float* acc,
                                            const float* __restrict__ Wg,
                                            const float* __restrict__ bg,
                                            const float* __restrict__ hsm,
                                            float* wbuf,
                                            int nchunks, int in_act,
                                            int half, int sid) {
#pragma unroll
    for (int k = 0; k < HALF_K; ++k) acc[k] = 0.f;

    load_chunk(wbuf, Wg, 0, in_act);
    cp_commit();

    for (int c = 0; c < nchunks; ++c) {
        int cur = c & 1;
        __syncthreads();                                // (A) prev compute done -> buffer reusable
        if (c + 1 < nchunks) {
            load_chunk(wbuf + (cur ^ 1) * CH * HID, Wg, c + 1, in_act);
            cp_commit();
            cp_wait1();                                 // chunk c landed
        } else {
            cp_wait0();
        }
        __syncthreads();                                // (B) chunk c visible to all

        float hreg[CH];
#pragma unroll
        for (int jj = 0; jj < CH; ++jj)
            hreg[jj] = hsm[(c * CH + jj) * TSAMP + sid];

        const float4* wb = reinterpret_cast<const float4*>(wbuf + cur * CH * HID)
                           + half * (HALF_K / 4);
#pragma unroll
        for (int jj = 0; jj < CH; ++jj) {
            float hv = hreg[jj];
#pragma unroll
            for (int k4 = 0; k4 < HALF_K / 4; ++k4) {
                float4 w = wb[jj * (HID / 4) + k4];
                acc[4 * k4 + 0] = fmaf(hv, w.x, acc[4 * k4 + 0]);
                acc[4 * k4 + 1] = fmaf(hv, w.y, acc[4 * k4 + 1]);
                acc[4 * k4 + 2] = fmaf(hv, w.z, acc[4 * k4 + 2]);
                acc[4 * k4 + 3] = fmaf(hv, w.w, acc[4 * k4 + 3]);
            }
        }
    }
    __syncthreads();                                    // (C) all h reads done -> safe to overwrite h

#pragma unroll
    for (int k = 0; k < HALF_K; ++k)
        acc[k] += __ldg(&bg[half * HALF_K + k]);
}

__global__ __launch_bounds__(NTHREADS, 1)
void ensemble_env_prob_kernel(
    const float* __restrict__ s, const float* __restrict__ a,
    const float* __restrict__ W1, const float* __restrict__ b1,
    const float* __restrict__ Wh, const float* __restrict__ bh,
    const float* __restrict__ Wmu, const float* __restrict__ bmu,
    const float* __restrict__ Wsig, const float* __restrict__ bsig,
    const float* __restrict__ max_lv_s, const float* __restrict__ min_lv_s,
    const float* __restrict__ max_lv_r, const float* __restrict__ min_lv_r,
    float* __restrict__ out, int N)
{
    extern __shared__ float sm[];
    float* hsm  = sm;                       // HID x TSAMP
    float* wbuf = sm + HID * TSAMP;         // 2 x CH x HID

    const int tid  = threadIdx.x;
    const int sid  = tid & (TSAMP - 1);
    const int half = tid >> 7;              // 0: features [0,100), 1: [100,200)
    const int e    = blockIdx.y;
    const int n0   = blockIdx.x * TSAMP;

    // ---- stage x = concat(s, a) into activation columns (rows 38,39 zero-padded)
    for (int idx = tid; idx < IN_PAD * TSAMP; idx += NTHREADS) {
        int j  = idx / TSAMP;
        int ss = idx % TSAMP;
        int n  = n0 + ss;
        if (n >= N) n = N - 1;              // clamp (stores predicated later)
        float v = 0.f;
        if (j < S_DIM)       v = s[((size_t)n * ENS + e) * S_DIM + j];
        else if (j < IN_DIM) v = a[((size_t)n * ENS + e) * A_DIM + (j - S_DIM)];
        hsm[j * TSAMP + ss] = v;
    }
    // no explicit sync: dense_layer's (A)+(B) barriers order these writes before reads

    float acc[HALF_K];

    // ---- layer 1: 38 -> 200
    dense_layer(acc, W1 + (size_t)e * IN_DIM * HID, b1 + (size_t)e * HID,
                hsm, wbuf, IN_PAD / CH, IN_DIM, half, sid);
#pragma unroll
    for (int k = 0; k < HALF_K; ++k)
        hsm[(half * HALF_K + k) * TSAMP + sid] = swishf(acc[k]);

    // ---- hidden layers: 200 -> 200, x3
    for (int l = 0; l < NHID; ++l) {
        dense_layer(acc, Wh + ((size_t)l * ENS + e) * HID * HID,
                    bh + ((size_t)l * ENS + e) * HID,
                    hsm, wbuf, HID / CH, HID, half, sid);
#pragma unroll
        for (int k = 0; k < HALF_K; ++k)
            hsm[(half * HALF_K + k) * TSAMP + sid] = swishf(acc[k]);
    }

    // ---- epilogue: half 0 computes mu (31), half 1 computes sigma (31)
    float oacc[32];
#pragma unroll
    for (int o = 0; o < 32; ++o) oacc[o] = 0.f;

    for (int c = 0; c < HID / CH; ++c) {
        __syncthreads();                    // prev iter's wbuf reads done
        // stage [mu | sig] chunk: 2 mats x CH rows x 32 cols (col 31 zero pad)
        for (int idx = tid; idx < 512; idx += NTHREADS) {
            int m   = idx >> 8;
            int rem = idx & 255;
            int jj  = rem >> 5;
            int o   = rem & 31;
            float v = 0.f;
            if (o < OUT_DIM) {
                const float* src = (m ? Wsig : Wmu)
                                   + (size_t)e * HID * OUT_DIM
                                   + (size_t)(c * CH + jj) * OUT_DIM + o;
                v = __ldg(src);
            }
            wbuf[idx] = v;
        }
        __syncthreads();

        float hreg[CH];
#pragma unroll
        for (int jj = 0; jj < CH; ++jj)
            hreg[jj] = hsm[(c * CH + jj) * TSAMP + sid];

        const float4* wb = reinterpret_cast<const float4*>(wbuf) + half * 64;
#pragma unroll
        for (int jj = 0; jj < CH; ++jj) {
            float hv = hreg[jj];
#pragma unroll
            for (int o4 = 0; o4 < 8; ++o4) {
                float4 w = wb[jj * 8 + o4];
                oacc[4 * o4 + 0] = fmaf(hv, w.x, oacc[4 * o4 + 0]);
                oacc[4 * o4 + 1] = fmaf(hv, w.y, oacc[4 * o4 + 1]);
                oacc[4 * o4 + 2] = fmaf(hv, w.z, oacc[4 * o4 + 2]);
                oacc[4 * o4 + 3] = fmaf(hv, w.w, oacc[4 * o4 + 3]);
            }
        }
    }

    const float* bo = (half ? bsig : bmu) + (size_t)e * OUT_DIM;
#pragma unroll
    for (int o = 0; o < OUT_DIM; ++o) oacc[o] += __ldg(&bo[o]);

    // ---- final transforms + stores
    const int n = n0 + sid;
    if (n < N) {
        const size_t base = (size_t)n * ENS + e;
        const size_t NT   = (size_t)N * ENS;
        if (half == 0) {
            // ds_mu [N,ENS,30] at 0 ; r_mu [N,ENS,1] at NT*60
#pragma unroll
            for (int d = 0; d < S_DIM; ++d)
                out[base * S_DIM + d] = oacc[d];
            out[NT * 60 + base] = oacc[S_DIM];
        } else {
            // ds_sg [N,ENS,30] at NT*30 ; r_sg [N,ENS,1] at NT*61
#pragma unroll
            for (int d = 0; d < S_DIM; ++d) {
                float x  = oacc[d];
                float mx = __ldg(&max_lv_s[d]);
                float mn = __ldg(&min_lv_s[d]);
                float t  = (mx - softplusf(mx - 2.0f * x)) * 0.5f;
                t        = (mn + softplusf(2.0f * t - mn)) * 0.5f;
                out[NT * 30 + base * S_DIM + d] = __expf(t);
            }
            {
                float x  = oacc[S_DIM];
                float mx = __ldg(&max_lv_r[0]);
                float mn = __ldg(&min_lv_r[0]);
                float t  = (mx - softplusf(mx - 2.0f * x)) * 0.5f;
                t        = (mn + softplusf(2.0f * t - mn)) * 0.5f;
                out[NT * 61 + base] = __expf(t);
            }
        }
    }
}

extern "C" void kernel_launch(void* const* d_in, const int* in_sizes, int n_in,
                              void* d_out, int out_size) {
    const float* s       = (const float*)d_in[0];
    const float* a       = (const float*)d_in[1];
    const float* W1      = (const float*)d_in[2];
    const float* b1      = (const float*)d_in[3];
    const float* Wh      = (const float*)d_in[4];
    const float* bh      = (const float*)d_in[5];
    const float* Wmu     = (const float*)d_in[6];
    const float* bmu     = (const float*)d_in[7];
    const float* Wsig    = (const float*)d_in[8];
    const float* bsig    = (const float*)d_in[9];
    const float* max_lvs = (const float*)d_in[10];
    const float* min_lvs = (const float*)d_in[11];
    const float* max_lvr = (const float*)d_in[12];
    const float* min_lvr = (const float*)d_in[13];
    float* out = (float*)d_out;

    const int N = in_sizes[0] / (ENS * S_DIM);   // 32768

    cudaFuncSetAttribute(ensemble_env_prob_kernel,
                         cudaFuncAttributeMaxDynamicSharedMemorySize, SMEM_BYTES);

    dim3 grid((N + TSAMP - 1) / TSAMP, ENS);
    ensemble_env_prob_kernel<<<grid, NTHREADS, SMEM_BYTES>>>(
        s, a, W1, b1, Wh, bh, Wmu, bmu, Wsig, bsig,
        max_lvs, min_lvs, max_lvr, min_lvr, out, N);
}

// round 6
// speedup vs baseline: 1.3305x; 1.3305x over previous
#include <cuda_runtime.h>
#include <cuda_bf16.h>
#include <cstdint>
#include <cstddef>

#define ENS     7
#define S_DIM   30
#define A_DIM   8
#define IN_DIM  38
#define HID     200
#define OUT_DIM 31
#define NHID    3
#define TSAMP   128
#define NTH     256

// ---- SMEM layout (bytes) ----
// A: 128 rows x 216 bf16 (stride 216 => 108 words: conflict-free frag LDS), hi+lo
// B: 208 rows(n) x 72 bf16 (stride 72 => 36 words: conflict-free frag LDS), hi+lo
#define AW      216                       // A row stride in bf16
#define BW      72                        // B row stride in bf16
#define SM_AHI  0
#define SM_ALO  (SM_AHI + 128 * AW * 2)   // 55296
#define SM_BHI  (SM_ALO + 128 * AW * 2)   // 110592
#define SM_BLO  (SM_BHI + 208 * BW * 2)   // 140544
#define SM_TOTAL (SM_BLO + 208 * BW * 2)  // 170496 bytes

__device__ __forceinline__ void mma16816(float* d, const uint32_t* a, const uint32_t* b) {
    asm volatile(
        "mma.sync.aligned.m16n8k16.row.col.f32.bf16.bf16.f32 "
        "{%0,%1,%2,%3}, {%4,%5,%6,%7}, {%8,%9}, {%0,%1,%2,%3};"
        : "+f"(d[0]), "+f"(d[1]), "+f"(d[2]), "+f"(d[3])
        : "r"(a[0]), "r"(a[1]), "r"(a[2]), "r"(a[3]),
          "r"(b[0]), "r"(b[1]));
}

__device__ __forceinline__ void split2(float x, uint16_t& hi, uint16_t& lo) {
    __nv_bfloat16 h = __float2bfloat16_rn(x);
    __nv_bfloat16 l = __float2bfloat16_rn(x - __bfloat162float(h));
    hi = __bfloat16_as_ushort(h);
    lo = __bfloat16_as_ushort(l);
}
__device__ __forceinline__ float swishf(float x) {
    return __fdividef(x, 1.0f + __expf(-x));
}
__device__ __forceinline__ float softplusf(float z) {
    return fmaxf(z, 0.0f) + log1pf(__expf(-fabsf(z)));
}
__device__ __forceinline__ float sig_transform(float x, float mx, float mn) {
    float t = (mx - softplusf(mx - 2.0f * x)) * 0.5f;
    t = (mn + softplusf(2.0f * t - mn)) * 0.5f;
    return __expf(t);
}

// ---- stage one K-chunk (64 k-rows) of W[krows x 200] into B (transposed, split) ----
__device__ __forceinline__ void stage_w(char* smc, const float* __restrict__ W,
                                        int krows, int c, int tid) {
    // idx -> (jp, n): warp reads 32 consecutive n of the same k-row pair (coalesced LDG)
    for (int idx = tid; idx < 32 * 208; idx += NTH) {
        int jp = idx / 208, n = idx % 208;
        int j = c * 64 + jp * 2;
        float w0 = 0.f, w1 = 0.f;
        if (n < HID) {
            if (j < krows)     w0 = __ldg(&W[(size_t)j * HID + n]);
            if (j + 1 < krows) w1 = __ldg(&W[(size_t)(j + 1) * HID + n]);
        }
        uint16_t h0, l0, h1, l1;
        split2(w0, h0, l0);
        split2(w1, h1, l1);
        uint32_t off = (uint32_t)(n * (BW * 2) + jp * 4);
        *(uint32_t*)(smc + SM_BHI + off) = (uint32_t)h0 | ((uint32_t)h1 << 16);
        *(uint32_t*)(smc + SM_BLO + off) = (uint32_t)l0 | ((uint32_t)l1 << 16);
    }
}

// ---- stage one K-chunk of packed head weights [mu(31)|pad|sig(31)|pad] (n=64) ----
__device__ __forceinline__ void stage_head(char* smc,
                                           const float* __restrict__ Wm,
                                           const float* __restrict__ Ws,
                                           int c, int tid) {
    for (int idx = tid; idx < 32 * 64; idx += NTH) {
        int jp = idx / 64, n = idx % 64;
        int j = c * 64 + jp * 2;
        float w0 = 0.f, w1 = 0.f;
        if (n < OUT_DIM) {
            if (j < HID)     w0 = __ldg(&Wm[(size_t)j * OUT_DIM + n]);
            if (j + 1 < HID) w1 = __ldg(&Wm[(size_t)(j + 1) * OUT_DIM + n]);
        } else if (n >= 32 && n < 32 + OUT_DIM) {
            int nn = n - 32;
            if (j < HID)     w0 = __ldg(&Ws[(size_t)j * OUT_DIM + nn]);
            if (j + 1 < HID) w1 = __ldg(&Ws[(size_t)(j + 1) * OUT_DIM + nn]);
        }
        uint16_t h0, l0, h1, l1;
        split2(w0, h0, l0);
        split2(w1, h1, l1);
        uint32_t off = (uint32_t)(n * (BW * 2) + jp * 4);
        *(uint32_t*)(smc + SM_BHI + off) = (uint32_t)h0 | ((uint32_t)h1 << 16);
        *(uint32_t*)(smc + SM_BLO + off) = (uint32_t)l0 | ((uint32_t)l1 << 16);
    }
}

// ---- MMA over the k-steps of one staged chunk (3-pass bf16 split) ----
// NT: n-tiles per warp; NOFF: warp n-group stride
template <int NT, int NOFF>
__device__ __forceinline__ void mma_chunk(float acc[2][NT][4], const char* smc,
                                          int kglob, int nk, int wm, int wn, int lane) {
#pragma unroll
    for (int ks = 0; ks < 4; ++ks) {
        if (ks >= nk) break;
        const int k0 = kglob + ks * 16 + (lane & 3) * 2;
        const int r0 = wm * 32 + (lane >> 2);
        uint32_t ah[2][4], al[2][4];
#pragma unroll
        for (int mt = 0; mt < 2; ++mt) {
            int r = r0 + mt * 16;
            const char* pA = smc + SM_AHI;
            ah[mt][0] = *(const uint32_t*)(pA + r * (AW * 2) + k0 * 2);
            ah[mt][1] = *(const uint32_t*)(pA + (r + 8) * (AW * 2) + k0 * 2);
            ah[mt][2] = *(const uint32_t*)(pA + r * (AW * 2) + (k0 + 8) * 2);
            ah[mt][3] = *(const uint32_t*)(pA + (r + 8) * (AW * 2) + (k0 + 8) * 2);
            const char* pL = smc + SM_ALO;
            al[mt][0] = *(const uint32_t*)(pL + r * (AW * 2) + k0 * 2);
            al[mt][1] = *(const uint32_t*)(pL + (r + 8) * (AW * 2) + k0 * 2);
            al[mt][2] = *(const uint32_t*)(pL + r * (AW * 2) + (k0 + 8) * 2);
            al[mt][3] = *(const uint32_t*)(pL + (r + 8) * (AW * 2) + (k0 + 8) * 2);
        }
        const int kk0 = ks * 16 + (lane & 3) * 2;
#pragma unroll
        for (int nt = 0; nt < NT; ++nt) {
            int n = wn * NOFF + nt * 8 + (lane >> 2);
            uint32_t bh[2], bl[2];
            bh[0] = *(const uint32_t*)(smc + SM_BHI + n * (BW * 2) + kk0 * 2);
            bh[1] = *(const uint32_t*)(smc + SM_BHI + n * (BW * 2) + (kk0 + 8) * 2);
            bl[0] = *(const uint32_t*)(smc + SM_BLO + n * (BW * 2) + kk0 * 2);
            bl[1] = *(const uint32_t*)(smc + SM_BLO + n * (BW * 2) + (kk0 + 8) * 2);
#pragma unroll
            for (int mt = 0; mt < 2; ++mt) {
                mma16816(acc[mt][nt], ah[mt], bh);   // hi*hi
                mma16816(acc[mt][nt], al[mt], bh);   // lo*hi
                mma16816(acc[mt][nt], ah[mt], bl);   // hi*lo
            }
        }
    }
}

__global__ __launch_bounds__(NTH, 1)
void ensemble_env_prob_hmma(
    const float* __restrict__ s, const float* __restrict__ a,
    const float* __restrict__ W1, const float* __restrict__ b1,
    const float* __restrict__ Wh, const float* __restrict__ bh,
    const float* __restrict__ Wmu, const float* __restrict__ bmu,
    const float* __restrict__ Wsig, const float* __restrict__ bsig,
    const float* __restrict__ max_lv_s, const float* __restrict__ min_lv_s,
    const float* __restrict__ max_lv_r, const float* __restrict__ min_lv_r,
    float* __restrict__ out, int N)
{
    extern __shared__ char smc[];
    const int tid  = threadIdx.x;
    const int wid  = tid >> 5;
    const int lane = tid & 31;
    const int wm   = wid & 3;          // 4 m-groups of 32 rows
    const int wn   = wid >> 2;         // 2 n-groups (104 cols main / 32 cols head)
    const int e    = blockIdx.y;
    const int n0   = blockIdx.x * TSAMP;

    // ---- zero A hi+lo (covers all k padding for every layer)
    for (int i = tid; i < 128 * AW; i += NTH) {
        ((uint32_t*)(smc + SM_AHI))[i] = 0u;
        ((uint32_t*)(smc + SM_ALO))[i] = 0u;
    }
    __syncthreads();

    // ---- stage x = concat(s, a), split into A
    for (int idx = tid; idx < TSAMP * IN_DIM; idx += NTH) {
        int m = idx / IN_DIM, k = idx % IN_DIM;
        int n = n0 + m;
        float v = (k < S_DIM)
                ? __ldg(&s[((size_t)n * ENS + e) * S_DIM + k])
                : __ldg(&a[((size_t)n * ENS + e) * A_DIM + (k - S_DIM)]);
        uint16_t h, l;
        split2(v, h, l);
        *(uint16_t*)(smc + SM_AHI + m * (AW * 2) + k * 2) = h;
        *(uint16_t*)(smc + SM_ALO + m * (AW * 2) + k * 2) = l;
    }
    // ordering vs MMA reads handled by syncthreads inside the layer loop

    float acc[2][13][4];

    // ================= layers 1..4 (output HID, swish epilogue) =================
#pragma unroll 1
    for (int l = 0; l < 1 + NHID; ++l) {
        const float* W  = (l == 0) ? (W1 + (size_t)e * IN_DIM * HID)
                                   : (Wh + ((size_t)(l - 1) * ENS + e) * HID * HID);
        const float* bi = (l == 0) ? (b1 + (size_t)e * HID)
                                   : (bh + ((size_t)(l - 1) * ENS + e) * HID);
        const int krows = (l == 0) ? IN_DIM : HID;
        const int nks   = (l == 0) ? 3 : 13;
        const int nch   = (nks + 3) >> 2;

#pragma unroll
        for (int mt = 0; mt < 2; ++mt)
#pragma unroll
            for (int nt = 0; nt < 13; ++nt)
#pragma unroll
                for (int q = 0; q < 4; ++q) acc[mt][nt][q] = 0.f;

        for (int c = 0; c < nch; ++c) {
            __syncthreads();                     // prior chunk's B reads done
            stage_w(smc, W, krows, c, tid);
            __syncthreads();                     // chunk visible
            int nk = nks - 4 * c; if (nk > 4) nk = 4;
            mma_chunk<13, 104>(acc, smc, c * 64, nk, wm, wn, lane);
        }
        __syncthreads();                         // all A reads done before overwrite

        // ---- epilogue: +bias, swish, split, write back to A
        const int r0 = wm * 32 + (lane >> 2);
#pragma unroll
        for (int mt = 0; mt < 2; ++mt) {
#pragma unroll
            for (int nt = 0; nt < 13; ++nt) {
                int cc = wn * 104 + nt * 8 + (lane & 3) * 2;
                float b0 = __ldg(&bi[cc]);
                float b1v = __ldg(&bi[cc + 1]);
#pragma unroll
                for (int rp = 0; rp < 2; ++rp) {
                    int r = r0 + mt * 16 + rp * 8;
                    float h0 = swishf(acc[mt][nt][rp * 2]     + b0);
                    float h1 = swishf(acc[mt][nt][rp * 2 + 1] + b1v);
                    uint16_t h0h, h0l, h1h, h1l;
                    split2(h0, h0h, h0l);
                    split2(h1, h1h, h1l);
                    uint32_t off = (uint32_t)(r * (AW * 2) + cc * 2);
                    *(uint32_t*)(smc + SM_AHI + off) = (uint32_t)h0h | ((uint32_t)h1h << 16);
                    *(uint32_t*)(smc + SM_ALO + off) = (uint32_t)h0l | ((uint32_t)h1l << 16);
                }
            }
        }
        // next iteration's first __syncthreads orders these writes before MMA reads
    }

    // ================= head: packed [mu | sig], N=64 =================
    float hacc[2][4][4];
#pragma unroll
    for (int mt = 0; mt < 2; ++mt)
#pragma unroll
        for (int nt = 0; nt < 4; ++nt)
#pragma unroll
            for (int q = 0; q < 4; ++q) hacc[mt][nt][q] = 0.f;

    {
        const float* Wm = Wmu  + (size_t)e * HID * OUT_DIM;
        const float* Ws = Wsig + (size_t)e * HID * OUT_DIM;
        for (int c = 0; c < 4; ++c) {
            __syncthreads();
            stage_head(smc, Wm, Ws, c, tid);
            __syncthreads();
            int nk = 13 - 4 * c; if (nk > 4) nk = 4;
            mma_chunk<4, 32>(hacc, smc, c * 64, nk, wm, wn, lane);
        }
    }

    // ================= head epilogue: direct global stores =================
    {
        const size_t NT   = (size_t)N * ENS;
        const size_t NT30 = NT * 30, NT60 = NT * 60, NT61 = NT * 61;
        const float* bo = (wn == 0 ? bmu : bsig) + (size_t)e * OUT_DIM;
        const int r0 = wm * 32 + (lane >> 2);
#pragma unroll
        for (int mt = 0; mt < 2; ++mt) {
#pragma unroll
            for (int rp = 0; rp < 2; ++rp) {
                int row = r0 + mt * 16 + rp * 8;
                size_t base = ((size_t)(n0 + row) * ENS + e);
#pragma unroll
                for (int nt = 0; nt < 4; ++nt) {
#pragma unroll
                    for (int i = 0; i < 2; ++i) {
                        int col = nt * 8 + (lane & 3) * 2 + i;   // 0..31
                        float v = hacc[mt][nt][rp * 2 + i];
                        if (wn == 0) {
                            if (col < S_DIM)
                                out[base * S_DIM + col] = v + __ldg(&bo[col]);
                            else if (col == S_DIM)
                                out[NT60 + base] = v + __ldg(&bo[S_DIM]);
                        } else {
                            if (col < S_DIM) {
                                float x = v + __ldg(&bo[col]);
                                out[NT30 + base * S_DIM + col] =
                                    sig_transform(x, __ldg(&max_lv_s[col]),
                                                     __ldg(&min_lv_s[col]));
                            } else if (col == S_DIM) {
                                float x = v + __ldg(&bo[S_DIM]);
                                out[NT61 + base] =
                                    sig_transform(x, __ldg(&max_lv_r[0]),
                                                     __ldg(&min_lv_r[0]));
                            }
                        }
                    }
                }
            }
        }
    }
}

extern "C" void kernel_launch(void* const* d_in, const int* in_sizes, int n_in,
                              void* d_out, int out_size) {
    const float* s       = (const float*)d_in[0];
    const float* a       = (const float*)d_in[1];
    const float* W1      = (const float*)d_in[2];
    const float* b1      = (const float*)d_in[3];
    const float* Wh      = (const float*)d_in[4];
    const float* bh      = (const float*)d_in[5];
    const float* Wmu     = (const float*)d_in[6];
    const float* bmu     = (const float*)d_in[7];
    const float* Wsig    = (const float*)d_in[8];
    const float* bsig    = (const float*)d_in[9];
    const float* max_lvs = (const float*)d_in[10];
    const float* min_lvs = (const float*)d_in[11];
    const float* max_lvr = (const float*)d_in[12];
    const float* min_lvr = (const float*)d_in[13];
    float* out = (float*)d_out;

    const int N = in_sizes[0] / (ENS * S_DIM);   // 32768

    cudaFuncSetAttribute(ensemble_env_prob_hmma,
                         cudaFuncAttributeMaxDynamicSharedMemorySize, SM_TOTAL);

    dim3 grid(N / TSAMP, ENS);
    ensemble_env_prob_hmma<<<grid, NTH, SM_TOTAL>>>(
        s, a, W1, b1, Wh, bh, Wmu, bmu, Wsig, bsig,
        max_lvs, min_lvs, max_lvr, min_lvr, out, N);
}

// round 7
// speedup vs baseline: 1.5538x; 1.1679x over previous
#include <cuda_runtime.h>
#include <cuda_fp16.h>
#include <cstdint>
#include <cstddef>

#define ENS     7
#define S_DIM   30
#define A_DIM   8
#define IN_DIM  38
#define HID     200
#define OUT_DIM 31
#define NHID    3
#define TSAMP   64
#define NTH     256

// ---- SMEM layout (bytes), per CTA = 86080 -> 2 CTAs/SM ----
// A: 64 rows x 216 halfs (stride 108 words: 12-stride banks, conflict-free), hi+lo
// B: 208 rows x 74 halfs (stride 37 words: 5-coprime banks), hi only (fp16 2-pass)
#define AW      216
#define BW      74
#define SM_AHI  0
#define SM_ALO  (64 * AW * 2)             // 27648
#define SM_BHI  (2 * 64 * AW * 2)         // 55296
#define SM_TOTAL (SM_BHI + 208 * BW * 2)  // 86080

__device__ __forceinline__ void mma16816(float* d, const uint32_t* a, const uint32_t* b) {
    asm volatile(
        "mma.sync.aligned.m16n8k16.row.col.f32.f16.f16.f32 "
        "{%0,%1,%2,%3}, {%4,%5,%6,%7}, {%8,%9}, {%0,%1,%2,%3};"
        : "+f"(d[0]), "+f"(d[1]), "+f"(d[2]), "+f"(d[3])
        : "r"(a[0]), "r"(a[1]), "r"(a[2]), "r"(a[3]),
          "r"(b[0]), "r"(b[1]));
}

__device__ __forceinline__ uint32_t pack2h(float x, float y) {
    __half2 h = __floats2half2_rn(x, y);
    return *reinterpret_cast<uint32_t*>(&h);
}
__device__ __forceinline__ float swishf(float x) {
    return __fdividef(x, 1.0f + __expf(-x));
}
__device__ __forceinline__ float softplusf(float z) {
    return fmaxf(z, 0.0f) + log1pf(__expf(-fabsf(z)));
}
__device__ __forceinline__ float sig_transform(float x, float mx, float mn) {
    float t = (mx - softplusf(mx - 2.0f * x)) * 0.5f;
    t = (mn + softplusf(2.0f * t - mn)) * 0.5f;
    return __expf(t);
}

// ---- stage one 64-k chunk of W[krows x 200] into B (transposed, fp16) ----
// lane -> n (coalesced LDG, conflict-free STS with 37-word stride)
__device__ __forceinline__ void stage_w(char* smc, const float* __restrict__ W,
                                        int krows, int c, int tid) {
#pragma unroll 4
    for (int it = 0; it < 32; ++it) {
        int n = tid;
        if (n < 208) {
            int j = c * 64 + 2 * it;
            float w0 = 0.f, w1 = 0.f;
            if (n < HID) {
                if (j < krows)     w0 = __ldg(&W[(size_t)j * HID + n]);
                if (j + 1 < krows) w1 = __ldg(&W[(size_t)(j + 1) * HID + n]);
            }
            *(uint32_t*)(smc + SM_BHI + n * (BW * 2) + it * 4) = pack2h(w0, w1);
        }
    }
}

// ---- stage head chunk: packed cols [mu(31)|pad|sig(31)|pad], n = 64 ----
__device__ __forceinline__ void stage_head(char* smc,
                                           const float* __restrict__ Wm,
                                           const float* __restrict__ Ws,
                                           int c, int tid) {
#pragma unroll
    for (int it = 0; it < 8; ++it) {
        int idx = it * NTH + tid;          // 2048
        int jp = idx >> 6;                 // 0..31
        int n  = idx & 63;
        int j  = c * 64 + 2 * jp;
        float w0 = 0.f, w1 = 0.f;
        if (n < OUT_DIM) {
            if (j < HID)     w0 = __ldg(&Wm[(size_t)j * OUT_DIM + n]);
            if (j + 1 < HID) w1 = __ldg(&Wm[(size_t)(j + 1) * OUT_DIM + n]);
        } else if (n >= 32 && n < 32 + OUT_DIM) {
            int nn = n - 32;
            if (j < HID)     w0 = __ldg(&Ws[(size_t)j * OUT_DIM + nn]);
            if (j + 1 < HID) w1 = __ldg(&Ws[(size_t)(j + 1) * OUT_DIM + nn]);
        }
        *(uint32_t*)(smc + SM_BHI + n * (BW * 2) + jp * 4) = pack2h(w0, w1);
    }
}

// ---- MMA over staged chunk: fp16 2-pass (A_hi*B + A_lo*B) ----
template <int NT, int NOFF>
__device__ __forceinline__ void mma_chunk(float acc[NT][4], const char* smc,
                                          int c64, int nk, int wm, int wn, int lane) {
#pragma unroll
    for (int ks = 0; ks < 4; ++ks) {
        if (ks >= nk) break;
        const int kB = ks * 16 + (lane & 3) * 2;   // B col within chunk
        const int kA = c64 + kB;                   // A col absolute
        const int r  = wm * 16 + (lane >> 2);
        uint32_t ah[4], al[4];
        {
            const char* pH = smc + SM_AHI;
            ah[0] = *(const uint32_t*)(pH + r * (AW * 2) + kA * 2);
            ah[1] = *(const uint32_t*)(pH + (r + 8) * (AW * 2) + kA * 2);
            ah[2] = *(const uint32_t*)(pH + r * (AW * 2) + (kA + 8) * 2);
            ah[3] = *(const uint32_t*)(pH + (r + 8) * (AW * 2) + (kA + 8) * 2);
            const char* pL = smc + SM_ALO;
            al[0] = *(const uint32_t*)(pL + r * (AW * 2) + kA * 2);
            al[1] = *(const uint32_t*)(pL + (r + 8) * (AW * 2) + kA * 2);
            al[2] = *(const uint32_t*)(pL + r * (AW * 2) + (kA + 8) * 2);
            al[3] = *(const uint32_t*)(pL + (r + 8) * (AW * 2) + (kA + 8) * 2);
        }
#pragma unroll
        for (int nt = 0; nt < NT; ++nt) {
            int n = wn * NOFF + nt * 8 + (lane >> 2);
            const char* pB = smc + SM_BHI + n * (BW * 2);
            uint32_t b[2];
            b[0] = *(const uint32_t*)(pB + kB * 2);
            b[1] = *(const uint32_t*)(pB + (kB + 8) * 2);
            mma16816(acc[nt], ah, b);
            mma16816(acc[nt], al, b);
        }
    }
}

__global__ __launch_bounds__(NTH, 2)
void ensemble_env_prob_hmma2(
    const float* __restrict__ s, const float* __restrict__ a,
    const float* __restrict__ W1, const float* __restrict__ b1,
    const float* __restrict__ Wh, const float* __restrict__ bh,
    const float* __restrict__ Wmu, const float* __restrict__ bmu,
    const float* __restrict__ Wsig, const float* __restrict__ bsig,
    const float* __restrict__ max_lv_s, const float* __restrict__ min_lv_s,
    const float* __restrict__ max_lv_r, const float* __restrict__ min_lv_r,
    float* __restrict__ out, int N)
{
    extern __shared__ char smc[];
    const int tid  = threadIdx.x;
    const int wid  = tid >> 5;
    const int lane = tid & 31;
    const int wm   = wid & 3;          // 4 m-groups x 16 rows
    const int wn   = wid >> 2;         // 2 n-groups (104 cols main / 32 head)
    const int e    = blockIdx.y;
    const int n0   = blockIdx.x * TSAMP;

    // ---- zero A hi+lo (covers all k padding: cols [38,216) / [200,216))
    for (int i = tid; i < (2 * 64 * AW) / 2; i += NTH)
        ((uint32_t*)smc)[i] = 0u;
    __syncthreads();

    // ---- stage x = concat(s, a), fp16 split into A
#pragma unroll
    for (int it = 0; it < 16; ++it) {
        int idx = it * NTH + tid;          // 4096 = 64 rows x 64 slots
        int m = idx >> 6, k = idx & 63;
        if (k < IN_DIM) {
            int n = n0 + m;
            float v = (k < S_DIM)
                    ? __ldg(&s[((size_t)n * ENS + e) * S_DIM + k])
                    : __ldg(&a[((size_t)n * ENS + e) * A_DIM + (k - S_DIM)]);
            __half h = __float2half_rn(v);
            __half l = __float2half_rn(v - __half2float(h));
            *(uint16_t*)(smc + SM_AHI + m * (AW * 2) + k * 2) = __half_as_ushort(h);
            *(uint16_t*)(smc + SM_ALO + m * (AW * 2) + k * 2) = __half_as_ushort(l);
        }
    }

    float acc[13][4];

    // ================= layers 1..4 (swish epilogue back into A) =================
#pragma unroll 1
    for (int l = 0; l < 1 + NHID; ++l) {
        const float* W  = (l == 0) ? (W1 + (size_t)e * IN_DIM * HID)
                                   : (Wh + ((size_t)(l - 1) * ENS + e) * HID * HID);
        const float* bi = (l == 0) ? (b1 + (size_t)e * HID)
                                   : (bh + ((size_t)(l - 1) * ENS + e) * HID);
        const int krows = (l == 0) ? IN_DIM : HID;
        const int nks   = (l == 0) ? 3 : 13;
        const int nch   = (nks + 3) >> 2;

#pragma unroll
        for (int nt = 0; nt < 13; ++nt)
#pragma unroll
            for (int q = 0; q < 4; ++q) acc[nt][q] = 0.f;

        for (int c = 0; c < nch; ++c) {
            __syncthreads();                  // prev B reads / A-epilogue writes done
            stage_w(smc, W, krows, c, tid);
            __syncthreads();                  // chunk visible
            int nk = nks - 4 * c; if (nk > 4) nk = 4;
            mma_chunk<13, 104>(acc, smc, c * 64, nk, wm, wn, lane);
        }
        __syncthreads();                      // all A reads done before overwrite

        // ---- epilogue: +bias, swish, fp16 split, back into A (cols < 200 only)
        const int rr = wm * 16 + (lane >> 2);
#pragma unroll
        for (int nt = 0; nt < 13; ++nt) {
            int cc = wn * 104 + nt * 8 + (lane & 3) * 2;
            if (cc < HID) {
                float b0  = __ldg(&bi[cc]);
                float b1v = __ldg(&bi[cc + 1]);
#pragma unroll
                for (int rp = 0; rp < 2; ++rp) {
                    int row = rr + rp * 8;
                    float h0 = swishf(acc[nt][rp * 2]     + b0);
                    float h1 = swishf(acc[nt][rp * 2 + 1] + b1v);
                    __half h0h = __float2half_rn(h0);
                    __half h1h = __float2half_rn(h1);
                    float r0 = h0 - __half2float(h0h);
                    float r1 = h1 - __half2float(h1h);
                    uint32_t off = (uint32_t)(row * (AW * 2) + cc * 2);
                    *(uint32_t*)(smc + SM_AHI + off) =
                        (uint32_t)__half_as_ushort(h0h) |
                        ((uint32_t)__half_as_ushort(h1h) << 16);
                    *(uint32_t*)(smc + SM_ALO + off) = pack2h(r0, r1);
                }
            }
        }
    }

    // ================= head: packed [mu | sig], N = 64 =================
#pragma unroll
    for (int nt = 0; nt < 4; ++nt)
#pragma unroll
        for (int q = 0; q < 4; ++q) acc[nt][q] = 0.f;

    {
        const float* Wm = Wmu  + (size_t)e * HID * OUT_DIM;
        const float* Ws = Wsig + (size_t)e * HID * OUT_DIM;
        float hacc4[4][4];   // alias view not needed; reuse acc[0..3]
        (void)hacc4;
        for (int c = 0; c < 4; ++c) {
            __syncthreads();
            stage_head(smc, Wm, Ws, c, tid);
            __syncthreads();
            int nk = 13 - 4 * c; if (nk > 4) nk = 4;
            mma_chunk<4, 32>(acc, smc, c * 64, nk, wm, wn, lane);
        }
    }

    // ================= head epilogue: direct global stores =================
    {
        const size_t NT_  = (size_t)N * ENS;
        const size_t NT30 = NT_ * 30, NT60 = NT_ * 60, NT61 = NT_ * 61;
        const float* bo = (wn == 0 ? bmu : bsig) + (size_t)e * OUT_DIM;
        const int rr = wm * 16 + (lane >> 2);
#pragma unroll
        for (int rp = 0; rp < 2; ++rp) {
            int row = rr + rp * 8;
            size_t base = ((size_t)(n0 + row) * ENS + e);
#pragma unroll
            for (int nt = 0; nt < 4; ++nt) {
#pragma unroll
                for (int i = 0; i < 2; ++i) {
                    int col = nt * 8 + (lane & 3) * 2 + i;   // 0..31
                    float v = acc[nt][rp * 2 + i];
                    if (wn == 0) {
                        if (col < S_DIM)
                            out[base * S_DIM + col] = v + __ldg(&bo[col]);
                        else if (col == S_DIM)
                            out[NT60 + base] = v + __ldg(&bo[S_DIM]);
                    } else {
                        if (col < S_DIM) {
                            float x = v + __ldg(&bo[col]);
                            out[NT30 + base * S_DIM + col] =
                                sig_transform(x, __ldg(&max_lv_s[col]),
                                                 __ldg(&min_lv_s[col]));
                        } else if (col == S_DIM) {
                            float x = v + __ldg(&bo[S_DIM]);
                            out[NT61 + base] =
                                sig_transform(x, __ldg(&max_lv_r[0]),
                                                 __ldg(&min_lv_r[0]));
                        }
                    }
                }
            }
        }
    }
}

extern "C" void kernel_launch(void* const* d_in, const int* in_sizes, int n_in,
                              void* d_out, int out_size) {
    const float* s       = (const float*)d_in[0];
    const float* a       = (const float*)d_in[1];
    const float* W1      = (const float*)d_in[2];
    const float* b1      = (const float*)d_in[3];
    const float* Wh      = (const float*)d_in[4];
    const float* bh      = (const float*)d_in[5];
    const float* Wmu     = (const float*)d_in[6];
    const float* bmu     = (const float*)d_in[7];
    const float* Wsig    = (const float*)d_in[8];
    const float* bsig    = (const float*)d_in[9];
    const float* max_lvs = (const float*)d_in[10];
    const float* min_lvs = (const float*)d_in[11];
    const float* max_lvr = (const float*)d_in[12];
    const float* min_lvr = (const float*)d_in[13];
    float* out = (float*)d_out;

    const int N = in_sizes[0] / (ENS * S_DIM);   // 32768

    cudaFuncSetAttribute(ensemble_env_prob_hmma2,
                         cudaFuncAttributeMaxDynamicSharedMemorySize, SM_TOTAL);

    dim3 grid(N / TSAMP, ENS);                   // 512 x 7 = 3584 CTAs
    ensemble_env_prob_hmma2<<<grid, NTH, SM_TOTAL>>>(
        s, a, W1, b1, Wh, bh, Wmu, bmu, Wsig, bsig,
        max_lvs, min_lvs, max_lvr, min_lvr, out, N);
}

// round 8
// speedup vs baseline: 2.5648x; 1.6507x over previous
#include <cuda_runtime.h>
#include <cuda_fp16.h>
#include <cstdint>
#include <cstddef>

#define ENS     7
#define S_DIM   30
#define A_DIM   8
#define IN_DIM  38
#define HID     200
#define OUT_DIM 31
#define NHID    3
#define TSAMP   64
#define NTH     256

// ---- SMEM layout (bytes), per CTA = 72768 -> 2 CTAs/SM ----
// A: 64 rows x 216 halfs (stride 108 words -> conflict-free frag LDS), hi+lo
// B: 208 rows x 42 halfs (stride 21 words, coprime 32 -> conflict-free STS),
//    one 32-k chunk, fp16 (weights rounded to fp16; A carries hi+lo)
#define AW      216
#define BWH     42                        // B row stride in halfs
#define SM_AHI  0
#define SM_ALO  (64 * AW * 2)             // 27648
#define SM_B    (2 * 64 * AW * 2)         // 55296
#define SM_TOTAL (SM_B + 208 * BWH * 2)   // 72768

__device__ __forceinline__ void mma16816(float* d, const uint32_t* a, const uint32_t* b) {
    asm volatile(
        "mma.sync.aligned.m16n8k16.row.col.f32.f16.f16.f32 "
        "{%0,%1,%2,%3}, {%4,%5,%6,%7}, {%8,%9}, {%0,%1,%2,%3};"
        : "+f"(d[0]), "+f"(d[1]), "+f"(d[2]), "+f"(d[3])
        : "r"(a[0]), "r"(a[1]), "r"(a[2]), "r"(a[3]),
          "r"(b[0]), "r"(b[1]));
}

__device__ __forceinline__ uint32_t pack2h(float x, float y) {
    __half2 h = __floats2half2_rn(x, y);
    return *reinterpret_cast<uint32_t*>(&h);
}
__device__ __forceinline__ float swishf(float x) {
    return __fdividef(x, 1.0f + __expf(-x));
}
__device__ __forceinline__ float softplusf(float z) {
    return fmaxf(z, 0.0f) + log1pf(__expf(-fabsf(z)));
}
__device__ __forceinline__ float sig_transform(float x, float mx, float mn) {
    float t = (mx - softplusf(mx - 2.0f * x)) * 0.5f;
    t = (mn + softplusf(2.0f * t - mn)) * 0.5f;
    return __expf(t);
}

// ======== main-layer staging: 32-k chunk of W[krows x 200], 13 pairs/thread ========
// pair gid = p*256+tid -> j2 = gid/208 (k-pair row), n = gid%208 (coalesced LDG)
__device__ __forceinline__ void ldg_chunk(float* pre, const float* __restrict__ W,
                                          int krows, int c, int tid) {
#pragma unroll
    for (int p = 0; p < 13; ++p) {
        int gid = p * NTH + tid;
        int j2 = gid / 208, n = gid % 208;
        int j = c * 32 + j2 * 2;
        float w0 = 0.f, w1 = 0.f;
        if (n < HID) {
            if (j < krows)     w0 = __ldg(&W[(size_t)j * HID + n]);
            if (j + 1 < krows) w1 = __ldg(&W[(size_t)(j + 1) * HID + n]);
        }
        pre[2 * p]     = w0;
        pre[2 * p + 1] = w1;
    }
}
__device__ __forceinline__ void sts_chunk(const float* pre, char* smc, int tid) {
#pragma unroll
    for (int p = 0; p < 13; ++p) {
        int gid = p * NTH + tid;
        int j2 = gid / 208, n = gid % 208;
        *(uint32_t*)(smc + SM_B + n * (BWH * 2) + j2 * 4) =
            pack2h(pre[2 * p], pre[2 * p + 1]);
    }
}

// ======== head staging: 32-k chunk of packed [mu(31)|pad|sig(31)|pad], n=64 ========
__device__ __forceinline__ void ldg_head(float* pre,
                                         const float* __restrict__ Wm,
                                         const float* __restrict__ Ws,
                                         int c, int tid) {
#pragma unroll
    for (int p = 0; p < 4; ++p) {
        int gid = p * NTH + tid;          // 1024 pairs
        int j2 = gid >> 6, n = gid & 63;
        int j = c * 32 + j2 * 2;
        float w0 = 0.f, w1 = 0.f;
        if (n < OUT_DIM) {
            if (j < HID)     w0 = __ldg(&Wm[(size_t)j * OUT_DIM + n]);
            if (j + 1 < HID) w1 = __ldg(&Wm[(size_t)(j + 1) * OUT_DIM + n]);
        } else if (n >= 32 && n < 32 + OUT_DIM) {
            int nn = n - 32;
            if (j < HID)     w0 = __ldg(&Ws[(size_t)j * OUT_DIM + nn]);
            if (j + 1 < HID) w1 = __ldg(&Ws[(size_t)(j + 1) * OUT_DIM + nn]);
        }
        pre[2 * p]     = w0;
        pre[2 * p + 1] = w1;
    }
}
__device__ __forceinline__ void sts_head(const float* pre, char* smc, int tid) {
#pragma unroll
    for (int p = 0; p < 4; ++p) {
        int gid = p * NTH + tid;
        int j2 = gid >> 6, n = gid & 63;
        *(uint32_t*)(smc + SM_B + n * (BWH * 2) + j2 * 4) =
            pack2h(pre[2 * p], pre[2 * p + 1]);
    }
}

// ======== MMA over one staged 32-k chunk: fp16 2-pass (A_hi*B + A_lo*B) ========
template <int NT, int NOFF>
__device__ __forceinline__ void mma_chunk32(float acc[NT][4], const char* smc,
                                            int c32, int nk, int wm, int wn, int lane) {
#pragma unroll
    for (int ks = 0; ks < 2; ++ks) {
        if (ks >= nk) break;
        const int kB = ks * 16 + (lane & 3) * 2;   // half index within chunk
        const int kA = c32 + kB;                   // absolute A col
        const int r  = wm * 16 + (lane >> 2);
        uint32_t ah[4], al[4];
        {
            const char* pH = smc + SM_AHI;
            ah[0] = *(const uint32_t*)(pH + r * (AW * 2) + kA * 2);
            ah[1] = *(const uint32_t*)(pH + (r + 8) * (AW * 2) + kA * 2);
            ah[2] = *(const uint32_t*)(pH + r * (AW * 2) + (kA + 8) * 2);
            ah[3] = *(const uint32_t*)(pH + (r + 8) * (AW * 2) + (kA + 8) * 2);
            const char* pL = smc + SM_ALO;
            al[0] = *(const uint32_t*)(pL + r * (AW * 2) + kA * 2);
            al[1] = *(const uint32_t*)(pL + (r + 8) * (AW * 2) + kA * 2);
            al[2] = *(const uint32_t*)(pL + r * (AW * 2) + (kA + 8) * 2);
            al[3] = *(const uint32_t*)(pL + (r + 8) * (AW * 2) + (kA + 8) * 2);
        }
#pragma unroll
        for (int nt = 0; nt < NT; ++nt) {
            int n = wn * NOFF + nt * 8 + (lane >> 2);
            const char* pB = smc + SM_B + n * (BWH * 2);
            uint32_t b[2];
            b[0] = *(const uint32_t*)(pB + kB * 2);
            b[1] = *(const uint32_t*)(pB + (kB + 8) * 2);
            mma16816(acc[nt], ah, b);   // hi pass
            mma16816(acc[nt], al, b);   // lo pass
        }
    }
}

__global__ __launch_bounds__(NTH, 2)
void ensemble_env_prob_hmma3(
    const float* __restrict__ s, const float* __restrict__ a,
    const float* __restrict__ W1, const float* __restrict__ b1,
    const float* __restrict__ Wh, const float* __restrict__ bh,
    const float* __restrict__ Wmu, const float* __restrict__ bmu,
    const float* __restrict__ Wsig, const float* __restrict__ bsig,
    const float* __restrict__ max_lv_s, const float* __restrict__ min_lv_s,
    const float* __restrict__ max_lv_r, const float* __restrict__ min_lv_r,
    float* __restrict__ out, int N)
{
    extern __shared__ char smc[];
    const int tid  = threadIdx.x;
    const int wid  = tid >> 5;
    const int lane = tid & 31;
    const int wm   = wid & 3;          // 4 m-groups x 16 rows
    const int wn   = wid >> 2;         // 2 n-groups (104 cols main / 32 head)
    const int e    = blockIdx.y;
    const int n0   = blockIdx.x * TSAMP;

    // ---- zero A hi+lo (covers all k padding)
    for (int i = tid; i < (2 * 64 * AW) / 2; i += NTH)
        ((uint32_t*)smc)[i] = 0u;
    __syncthreads();

    // ---- stage x = concat(s, a), fp16 split into A
#pragma unroll
    for (int it = 0; it < 16; ++it) {
        int idx = it * NTH + tid;          // 4096 = 64 rows x 64 slots
        int m = idx >> 6, k = idx & 63;
        if (k < IN_DIM) {
            int n = n0 + m;
            float v = (k < S_DIM)
                    ? __ldg(&s[((size_t)n * ENS + e) * S_DIM + k])
                    : __ldg(&a[((size_t)n * ENS + e) * A_DIM + (k - S_DIM)]);
            __half h = __float2half_rn(v);
            __half l = __float2half_rn(v - __half2float(h));
            *(uint16_t*)(smc + SM_AHI + m * (AW * 2) + k * 2) = __half_as_ushort(h);
            *(uint16_t*)(smc + SM_ALO + m * (AW * 2) + k * 2) = __half_as_ushort(l);
        }
    }

    float acc[13][4];
    float pre[26];

    // ================= layers 1..4 (swish epilogue back into A) =================
#pragma unroll 1
    for (int l = 0; l < 1 + NHID; ++l) {
        const float* W  = (l == 0) ? (W1 + (size_t)e * IN_DIM * HID)
                                   : (Wh + ((size_t)(l - 1) * ENS + e) * HID * HID);
        const float* bi = (l == 0) ? (b1 + (size_t)e * HID)
                                   : (bh + ((size_t)(l - 1) * ENS + e) * HID);
        const int krows = (l == 0) ? IN_DIM : HID;
        const int nks   = (l == 0) ? 3 : 13;   // 16-k steps
        const int nch   = (nks + 1) >> 1;      // 32-k chunks

#pragma unroll
        for (int nt = 0; nt < 13; ++nt)
#pragma unroll
            for (int q = 0; q < 4; ++q) acc[nt][q] = 0.f;

        ldg_chunk(pre, W, krows, 0, tid);          // prefetch chunk 0
#pragma unroll 1
        for (int c = 0; c < nch; ++c) {
            __syncthreads();                       // prev MMA done reading B / A-epi done
            sts_chunk(pre, smc, tid);              // land chunk c
            if (c + 1 < nch)
                ldg_chunk(pre, W, krows, c + 1, tid);   // issue next LDGs NOW
            __syncthreads();                       // chunk c visible
            int nk = nks - 2 * c; if (nk > 2) nk = 2;
            mma_chunk32<13, 104>(acc, smc, c * 32, nk, wm, wn, lane);  // overlaps LDG
        }
        __syncthreads();                           // all A reads done before overwrite

        // ---- epilogue: +bias, swish, fp16 split, back into A (cols < 200)
        const int rr = wm * 16 + (lane >> 2);
#pragma unroll
        for (int nt = 0; nt < 13; ++nt) {
            int cc = wn * 104 + nt * 8 + (lane & 3) * 2;
            if (cc < HID) {
                float b0  = __ldg(&bi[cc]);
                float b1v = __ldg(&bi[cc + 1]);
#pragma unroll
                for (int rp = 0; rp < 2; ++rp) {
                    int row = rr + rp * 8;
                    float h0 = swishf(acc[nt][rp * 2]     + b0);
                    float h1 = swishf(acc[nt][rp * 2 + 1] + b1v);
                    __half h0h = __float2half_rn(h0);
                    __half h1h = __float2half_rn(h1);
                    float r0 = h0 - __half2float(h0h);
                    float r1 = h1 - __half2float(h1h);
                    uint32_t off = (uint32_t)(row * (AW * 2) + cc * 2);
                    *(uint32_t*)(smc + SM_AHI + off) =
                        (uint32_t)__half_as_ushort(h0h) |
                        ((uint32_t)__half_as_ushort(h1h) << 16);
                    *(uint32_t*)(smc + SM_ALO + off) = pack2h(r0, r1);
                }
            }
        }
    }

    // ================= head: packed [mu | sig], N = 64, 7 chunks =================
#pragma unroll
    for (int nt = 0; nt < 4; ++nt)
#pragma unroll
        for (int q = 0; q < 4; ++q) acc[nt][q] = 0.f;

    {
        const float* Wm = Wmu  + (size_t)e * HID * OUT_DIM;
        const float* Ws = Wsig + (size_t)e * HID * OUT_DIM;
        ldg_head(pre, Wm, Ws, 0, tid);
#pragma unroll 1
        for (int c = 0; c < 7; ++c) {
            __syncthreads();
            sts_head(pre, smc, tid);
            if (c + 1 < 7) ldg_head(pre, Wm, Ws, c + 1, tid);
            __syncthreads();
            int nk = 13 - 2 * c; if (nk > 2) nk = 2;
            mma_chunk32<4, 32>(acc, smc, c * 32, nk, wm, wn, lane);
        }
    }

    // ================= head epilogue: direct global stores =================
    {
        const size_t NT_  = (size_t)N * ENS;
        const size_t NT30 = NT_ * 30, NT60 = NT_ * 60, NT61 = NT_ * 61;
        const float* bo = (wn == 0 ? bmu : bsig) + (size_t)e * OUT_DIM;
        const int rr = wm * 16 + (lane >> 2);
#pragma unroll
        for (int rp = 0; rp < 2; ++rp) {
            int row = rr + rp * 8;
            size_t base = ((size_t)(n0 + row) * ENS + e);
#pragma unroll
            for (int nt = 0; nt < 4; ++nt) {
#pragma unroll
                for (int i = 0; i < 2; ++i) {
                    int col = nt * 8 + (lane & 3) * 2 + i;   // 0..31
                    float v = acc[nt][rp * 2 + i];
                    if (wn == 0) {
                        if (col < S_DIM)
                            out[base * S_DIM + col] = v + __ldg(&bo[col]);
                        else if (col == S_DIM)
                            out[NT60 + base] = v + __ldg(&bo[S_DIM]);
                    } else {
                        if (col < S_DIM) {
                            float x = v + __ldg(&bo[col]);
                            out[NT30 + base * S_DIM + col] =
                                sig_transform(x, __ldg(&max_lv_s[col]),
                                                 __ldg(&min_lv_s[col]));
                        } else if (col == S_DIM) {
                            float x = v + __ldg(&bo[S_DIM]);
                            out[NT61 + base] =
                                sig_transform(x, __ldg(&max_lv_r[0]),
                                                 __ldg(&min_lv_r[0]));
                        }
                    }
                }
            }
        }
    }
}

extern "C" void kernel_launch(void* const* d_in, const int* in_sizes, int n_in,
                              void* d_out, int out_size) {
    const float* s       = (const float*)d_in[0];
    const float* a       = (const float*)d_in[1];
    const float* W1      = (const float*)d_in[2];
    const float* b1      = (const float*)d_in[3];
    const float* Wh      = (const float*)d_in[4];
    const float* bh      = (const float*)d_in[5];
    const float* Wmu     = (const float*)d_in[6];
    const float* bmu     = (const float*)d_in[7];
    const float* Wsig    = (const float*)d_in[8];
    const float* bsig    = (const float*)d_in[9];
    const float* max_lvs = (const float*)d_in[10];
    const float* min_lvs = (const float*)d_in[11];
    const float* max_lvr = (const float*)d_in[12];
    const float* min_lvr = (const float*)d_in[13];
    float* out = (float*)d_out;

    const int N = in_sizes[0] / (ENS * S_DIM);   // 32768

    cudaFuncSetAttribute(ensemble_env_prob_hmma3,
                         cudaFuncAttributeMaxDynamicSharedMemorySize, SM_TOTAL);

    dim3 grid(N / TSAMP, ENS);                   // 512 x 7 = 3584 CTAs
    ensemble_env_prob_hmma3<<<grid, NTH, SM_TOTAL>>>(
        s, a, W1, b1, Wh, bh, Wmu, bmu, Wsig, bsig,
        max_lvs, min_lvs, max_lvr, min_lvr, out, N);
}

// round 9
// speedup vs baseline: 3.0534x; 1.1905x over previous
#include <cuda_runtime.h>
#include <cuda_fp16.h>
#include <cstdint>
#include <cstddef>

#define ENS     7
#define S_DIM   30
#define A_DIM   8
#define IN_DIM  38
#define HID     200
#define OUT_DIM 31
#define NHID    3
#define TSAMP   64
#define NTH     256

// ---- SMEM layout (bytes), per CTA = 73216 -> 2 CTAs/SM ----
// A: 64 rows x 216 halfs (stride 108 words), hi+lo. ldmatrix phases conflict-free
//    (12r mod 32 bank groups disjoint).
// B: 224 rows x 40 halfs (stride 20 words): {20n mod 32}+[0,4) disjoint ->
//    conflict-free ldmatrix AND conflict-free STS with the (j2,n) decode below.
#define AW      216
#define BWH     40
#define SM_AHI  0
#define SM_ALO  (64 * AW * 2)             // 27648
#define SM_B    (2 * 64 * AW * 2)         // 55296
#define SM_TOTAL (SM_B + 224 * BWH * 2)   // 73216

__device__ __forceinline__ void mma16816(float* d, const uint32_t* a, const uint32_t* b) {
    asm volatile(
        "mma.sync.aligned.m16n8k16.row.col.f32.f16.f16.f32 "
        "{%0,%1,%2,%3}, {%4,%5,%6,%7}, {%8,%9}, {%0,%1,%2,%3};"
        : "+f"(d[0]), "+f"(d[1]), "+f"(d[2]), "+f"(d[3])
        : "r"(a[0]), "r"(a[1]), "r"(a[2]), "r"(a[3]),
          "r"(b[0]), "r"(b[1]));
}
__device__ __forceinline__ void ldsm4(uint32_t* r, uint32_t addr) {
    asm volatile("ldmatrix.sync.aligned.m8n8.x4.shared.b16 {%0,%1,%2,%3}, [%4];"
        : "=r"(r[0]), "=r"(r[1]), "=r"(r[2]), "=r"(r[3]) : "r"(addr));
}
__device__ __forceinline__ void ldsm2(uint32_t* r, uint32_t addr) {
    asm volatile("ldmatrix.sync.aligned.m8n8.x2.shared.b16 {%0,%1}, [%2];"
        : "=r"(r[0]), "=r"(r[1]) : "r"(addr));
}

__device__ __forceinline__ uint32_t pack2h(float x, float y) {
    __half2 h = __floats2half2_rn(x, y);
    return *reinterpret_cast<uint32_t*>(&h);
}
__device__ __forceinline__ float swishf(float x) {
    return __fdividef(x, 1.0f + __expf(-x));
}
__device__ __forceinline__ float softplusf(float z) {
    return fmaxf(z, 0.0f) + log1pf(__expf(-fabsf(z)));
}
__device__ __forceinline__ float sig_transform(float x, float mx, float mn) {
    float t = (mx - softplusf(mx - 2.0f * x)) * 0.5f;
    t = (mn + softplusf(2.0f * t - mn)) * 0.5f;
    return __expf(t);
}

// ---- staging decode: pair index q -> (j2 = k-pair 0..15, n) ----
// q bits: [2:0]=n_low, [6:3]=j2, [>=7]=n_high. Within a warp: 4 j2 x 8 consecutive n
// -> STS banks 20n+j2 all distinct (conflict-free), LDG 32B-segment coalesced.
#define DECODE_QN(q, j2, n) do { j2 = ((q) >> 3) & 15; n = ((q) & 7) | (((q) >> 7) << 3); } while (0)

// ======== main staging: one 32-k chunk of W[krows x 200] -> B (3584 pairs) ========
__device__ __forceinline__ void ldg_chunk(uint32_t* pre, const float* __restrict__ W,
                                          int krows, int c, int tid) {
#pragma unroll
    for (int p = 0; p < 14; ++p) {
        int q = p * NTH + tid, j2, n;
        DECODE_QN(q, j2, n);
        int j = c * 32 + 2 * j2;
        float w0 = 0.f, w1 = 0.f;
        if (n < HID) {
            if (j < krows)     w0 = __ldg(&W[(size_t)j * HID + n]);
            if (j + 1 < krows) w1 = __ldg(&W[(size_t)(j + 1) * HID + n]);
        }
        pre[p] = pack2h(w0, w1);
    }
}
__device__ __forceinline__ void sts_chunk(const uint32_t* pre, char* smc, int tid) {
#pragma unroll
    for (int p = 0; p < 14; ++p) {
        int q = p * NTH + tid, j2, n;
        DECODE_QN(q, j2, n);
        *(uint32_t*)(smc + SM_B + n * (BWH * 2) + j2 * 4) = pre[p];
    }
}

// ======== head staging: 32-k chunk of packed [mu(31)|pad|sig(31)|pad] (1024 pairs) ====
__device__ __forceinline__ void ldg_head(uint32_t* pre,
                                         const float* __restrict__ Wm,
                                         const float* __restrict__ Ws,
                                         int c, int tid) {
#pragma unroll
    for (int p = 0; p < 4; ++p) {
        int q = p * NTH + tid, j2, n;
        DECODE_QN(q, j2, n);               // q < 1024 -> n < 64
        int j = c * 32 + 2 * j2;
        float w0 = 0.f, w1 = 0.f;
        if (n < OUT_DIM) {
            if (j < HID)     w0 = __ldg(&Wm[(size_t)j * OUT_DIM + n]);
            if (j + 1 < HID) w1 = __ldg(&Wm[(size_t)(j + 1) * OUT_DIM + n]);
        } else if (n >= 32 && n < 32 + OUT_DIM) {
            int nn = n - 32;
            if (j < HID)     w0 = __ldg(&Ws[(size_t)j * OUT_DIM + nn]);
            if (j + 1 < HID) w1 = __ldg(&Ws[(size_t)(j + 1) * OUT_DIM + nn]);
        }
        pre[p] = pack2h(w0, w1);
    }
}
__device__ __forceinline__ void sts_head(const uint32_t* pre, char* smc, int tid) {
#pragma unroll
    for (int p = 0; p < 4; ++p) {
        int q = p * NTH + tid, j2, n;
        DECODE_QN(q, j2, n);
        *(uint32_t*)(smc + SM_B + n * (BWH * 2) + j2 * 4) = pre[p];
    }
}

__global__ __launch_bounds__(NTH, 2)
void ensemble_env_prob_hmma4(
    const float* __restrict__ s, const float* __restrict__ a,
    const float* __restrict__ W1, const float* __restrict__ b1,
    const float* __restrict__ Wh, const float* __restrict__ bh,
    const float* __restrict__ Wmu, const float* __restrict__ bmu,
    const float* __restrict__ Wsig, const float* __restrict__ bsig,
    const float* __restrict__ max_lv_s, const float* __restrict__ min_lv_s,
    const float* __restrict__ max_lv_r, const float* __restrict__ min_lv_r,
    float* __restrict__ out, int N)
{
    extern __shared__ char smc[];
    const uint32_t smb = (uint32_t)__cvta_generic_to_shared(smc);
    const int tid  = threadIdx.x;
    const int wid  = tid >> 5;
    const int lane = tid & 31;
    const int wm   = wid >> 2;         // 2 m-groups x 32 rows
    const int wn   = wid & 3;          // 4 n-groups x 56 cols (head: 16 cols)
    const int e    = blockIdx.y;
    const int n0   = blockIdx.x * TSAMP;

    // ldmatrix per-lane address components (constant all kernel)
    const int aRow0  = wm * 32 + (lane & 15);            // mf adds +16
    const int aColL  = (lane >> 4) * 8;                  // k sub-offset by lane
    const uint32_t aHiB = smb + SM_AHI + aRow0 * (AW * 2);
    const uint32_t aLoB = smb + SM_ALO + aRow0 * (AW * 2);
    const int bRowL  = (lane & 7) + ((lane >> 4) << 3);  // row-in-pair-of-tiles
    const int bKoffL = ((lane >> 3) & 1) * 8;            // k sub-offset by lane
    const uint32_t bBase = smb + SM_B + bRowL * (BWH * 2) + bKoffL * 2;

    // ---- zero A hi+lo (covers all k padding)
    for (int i = tid; i < (2 * 64 * AW) / 2; i += NTH)
        ((uint32_t*)smc)[i] = 0u;
    __syncthreads();

    // ---- stage x = concat(s, a), fp16 split into A
#pragma unroll
    for (int it = 0; it < 16; ++it) {
        int idx = it * NTH + tid;          // 4096 = 64 rows x 64 slots
        int m = idx >> 6, k = idx & 63;
        if (k < IN_DIM) {
            int n = n0 + m;
            float v = (k < S_DIM)
                    ? __ldg(&s[((size_t)n * ENS + e) * S_DIM + k])
                    : __ldg(&a[((size_t)n * ENS + e) * A_DIM + (k - S_DIM)]);
            __half h = __float2half_rn(v);
            __half l = __float2half_rn(v - __half2float(h));
            *(uint16_t*)(smc + SM_AHI + m * (AW * 2) + k * 2) = __half_as_ushort(h);
            *(uint16_t*)(smc + SM_ALO + m * (AW * 2) + k * 2) = __half_as_ushort(l);
        }
    }

    float acc[2][7][4];                    // [mf][nt][q]
    uint32_t pre[14];

    // ================= layers 1..4 (swish epilogue back into A) =================
#pragma unroll 1
    for (int l = 0; l < 1 + NHID; ++l) {
        const float* W  = (l == 0) ? (W1 + (size_t)e * IN_DIM * HID)
                                   : (Wh + ((size_t)(l - 1) * ENS + e) * HID * HID);
        const float* bi = (l == 0) ? (b1 + (size_t)e * HID)
                                   : (bh + ((size_t)(l - 1) * ENS + e) * HID);
        const int krows = (l == 0) ? IN_DIM : HID;
        const int nks   = (l == 0) ? 3 : 13;   // 16-k steps
        const int nch   = (nks + 1) >> 1;      // 32-k chunks

#pragma unroll
        for (int mf = 0; mf < 2; ++mf)
#pragma unroll
            for (int nt = 0; nt < 7; ++nt)
#pragma unroll
                for (int q = 0; q < 4; ++q) acc[mf][nt][q] = 0.f;

        ldg_chunk(pre, W, krows, 0, tid);
#pragma unroll 1
        for (int c = 0; c < nch; ++c) {
            __syncthreads();                       // prev MMA done with B / A-epi done
            sts_chunk(pre, smc, tid);
            if (c + 1 < nch) ldg_chunk(pre, W, krows, c + 1, tid);
            __syncthreads();                       // chunk visible
            const int nk = (nks - 2 * c > 2) ? 2 : (nks - 2 * c);
#pragma unroll
            for (int ks = 0; ks < 2; ++ks) {
                if (ks >= nk) break;
                const int kA = c * 32 + ks * 16 + aColL;
                uint32_t ah[2][4], al[2][4];
                ldsm4(ah[0], aHiB + kA * 2);
                ldsm4(al[0], aLoB + kA * 2);
                ldsm4(ah[1], aHiB + 16 * (AW * 2) + kA * 2);
                ldsm4(al[1], aLoB + 16 * (AW * 2) + kA * 2);
                const uint32_t bk = bBase + (ks * 16) * 2 + (wn * 56) * (BWH * 2);
#pragma unroll
                for (int ntp = 0; ntp < 3; ++ntp) {
                    uint32_t b4[4];
                    ldsm4(b4, bk + (ntp * 16) * (BWH * 2));
#pragma unroll
                    for (int mf = 0; mf < 2; ++mf) {
                        mma16816(acc[mf][2 * ntp],     ah[mf], b4);
                        mma16816(acc[mf][2 * ntp],     al[mf], b4);
                        mma16816(acc[mf][2 * ntp + 1], ah[mf], b4 + 2);
                        mma16816(acc[mf][2 * ntp + 1], al[mf], b4 + 2);
                    }
                }
                {
                    uint32_t b2[2];
                    ldsm2(b2, bk + 48 * (BWH * 2));
#pragma unroll
                    for (int mf = 0; mf < 2; ++mf) {
                        mma16816(acc[mf][6], ah[mf], b2);
                        mma16816(acc[mf][6], al[mf], b2);
                    }
                }
            }
        }
        __syncthreads();                           // all A reads done before overwrite

        // ---- epilogue: +bias, swish, fp16 split, back into A (cols < 200)
        const int rr = wm * 32 + (lane >> 2);
#pragma unroll
        for (int nt = 0; nt < 7; ++nt) {
            int cc = wn * 56 + nt * 8 + (lane & 3) * 2;
            if (cc < HID) {
                float b0  = __ldg(&bi[cc]);
                float b1v = __ldg(&bi[cc + 1]);
#pragma unroll
                for (int mf = 0; mf < 2; ++mf) {
#pragma unroll
                    for (int rp = 0; rp < 2; ++rp) {
                        int row = rr + mf * 16 + rp * 8;
                        float h0 = swishf(acc[mf][nt][rp * 2]     + b0);
                        float h1 = swishf(acc[mf][nt][rp * 2 + 1] + b1v);
                        __half h0h = __float2half_rn(h0);
                        __half h1h = __float2half_rn(h1);
                        float r0 = h0 - __half2float(h0h);
                        float r1 = h1 - __half2float(h1h);
                        uint32_t off = (uint32_t)(row * (AW * 2) + cc * 2);
                        *(uint32_t*)(smc + SM_AHI + off) =
                            (uint32_t)__half_as_ushort(h0h) |
                            ((uint32_t)__half_as_ushort(h1h) << 16);
                        *(uint32_t*)(smc + SM_ALO + off) = pack2h(r0, r1);
                    }
                }
            }
        }
    }

    // ================= head: packed [mu | sig], N = 64, warp covers 16 cols ========
#pragma unroll
    for (int mf = 0; mf < 2; ++mf)
#pragma unroll
        for (int nt = 0; nt < 2; ++nt)
#pragma unroll
            for (int q = 0; q < 4; ++q) acc[mf][nt][q] = 0.f;

    {
        const float* Wm = Wmu  + (size_t)e * HID * OUT_DIM;
        const float* Ws = Wsig + (size_t)e * HID * OUT_DIM;
        ldg_head(pre, Wm, Ws, 0, tid);
#pragma unroll 1
        for (int c = 0; c < 7; ++c) {
            __syncthreads();
            sts_head(pre, smc, tid);
            if (c + 1 < 7) ldg_head(pre, Wm, Ws, c + 1, tid);
            __syncthreads();
            const int nk = (13 - 2 * c > 2) ? 2 : (13 - 2 * c);
#pragma unroll
            for (int ks = 0; ks < 2; ++ks) {
                if (ks >= nk) break;
                const int kA = c * 32 + ks * 16 + aColL;
                uint32_t ah[2][4], al[2][4];
                ldsm4(ah[0], aHiB + kA * 2);
                ldsm4(al[0], aLoB + kA * 2);
                ldsm4(ah[1], aHiB + 16 * (AW * 2) + kA * 2);
                ldsm4(al[1], aLoB + 16 * (AW * 2) + kA * 2);
                uint32_t b4[4];
                ldsm4(b4, bBase + (ks * 16) * 2 + (wn * 16) * (BWH * 2));
#pragma unroll
                for (int mf = 0; mf < 2; ++mf) {
                    mma16816(acc[mf][0], ah[mf], b4);
                    mma16816(acc[mf][0], al[mf], b4);
                    mma16816(acc[mf][1], ah[mf], b4 + 2);
                    mma16816(acc[mf][1], al[mf], b4 + 2);
                }
            }
        }
    }

    // ================= head epilogue: direct global stores =================
    {
        const size_t NT_  = (size_t)N * ENS;
        const size_t NT30 = NT_ * 30, NT60 = NT_ * 60, NT61 = NT_ * 61;
        const bool  is_sig = (wn >= 2);
        const float* bo = (is_sig ? bsig : bmu) + (size_t)e * OUT_DIM;
        const int rr = wm * 32 + (lane >> 2);
#pragma unroll
        for (int mf = 0; mf < 2; ++mf) {
#pragma unroll
            for (int rp = 0; rp < 2; ++rp) {
                int row = rr + mf * 16 + rp * 8;
                size_t base = ((size_t)(n0 + row) * ENS + e);
#pragma unroll
                for (int nt = 0; nt < 2; ++nt) {
#pragma unroll
                    for (int i = 0; i < 2; ++i) {
                        int colg = wn * 16 + nt * 8 + (lane & 3) * 2 + i;  // 0..63
                        int col  = is_sig ? (colg - 32) : colg;            // 0..31
                        float v = acc[mf][nt][rp * 2 + i];
                        if (!is_sig) {
                            if (col < S_DIM)
                                out[base * S_DIM + col] = v + __ldg(&bo[col]);
                            else if (col == S_DIM)
                                out[NT60 + base] = v + __ldg(&bo[S_DIM]);
                        } else {
                            if (col < S_DIM) {
                                float x = v + __ldg(&bo[col]);
                                out[NT30 + base * S_DIM + col] =
                                    sig_transform(x, __ldg(&max_lv_s[col]),
                                                     __ldg(&min_lv_s[col]));
                            } else if (col == S_DIM) {
                                float x = v + __ldg(&bo[S_DIM]);
                                out[NT61 + base] =
                                    sig_transform(x, __ldg(&max_lv_r[0]),
                                                     __ldg(&min_lv_r[0]));
                            }
                        }
                    }
                }
            }
        }
    }
}

extern "C" void kernel_launch(void* const* d_in, const int* in_sizes, int n_in,
                              void* d_out, int out_size) {
    const float* s       = (const float*)d_in[0];
    const float* a       = (const float*)d_in[1];
    const float* W1      = (const float*)d_in[2];
    const float* b1      = (const float*)d_in[3];
    const float* Wh      = (const float*)d_in[4];
    const float* bh      = (const float*)d_in[5];
    const float* Wmu     = (const float*)d_in[6];
    const float* bmu     = (const float*)d_in[7];
    const float* Wsig    = (const float*)d_in[8];
    const float* bsig    = (const float*)d_in[9];
    const float* max_lvs = (const float*)d_in[10];
    const float* min_lvs = (const float*)d_in[11];
    const float* max_lvr = (const float*)d_in[12];
    const float* min_lvr = (const float*)d_in[13];
    float* out = (float*)d_out;

    const int N = in_sizes[0] / (ENS * S_DIM);   // 32768

    cudaFuncSetAttribute(ensemble_env_prob_hmma4,
                         cudaFuncAttributeMaxDynamicSharedMemorySize, SM_TOTAL);

    dim3 grid(N / TSAMP, ENS);                   // 512 x 7 = 3584 CTAs
    ensemble_env_prob_hmma4<<<grid, NTH, SM_TOTAL>>>(
        s, a, W1, b1, Wh, bh, Wmu, bmu, Wsig, bsig,
        max_lvs, min_lvs, max_lvr, min_lvr, out, N);
}

// round 11
// speedup vs baseline: 3.5021x; 1.1469x over previous
#include <cuda_runtime.h>
#include <cuda_fp16.h>
#include <cstdint>
#include <cstddef>

#define ENS     7
#define S_DIM   30
#define A_DIM   8
#define IN_DIM  38
#define HID     200
#define OUT_DIM 31
#define NHID    3
#define TSAMP   64
#define NTH     256

// ---- SMEM layout (bytes), per CTA = 45568 -> 2 CTAs/SM ----
// A: 64 rows x 216 halfs (stride 108 words), fp16. ldmatrix phases conflict-free.
// B: 224 rows x 40 halfs (stride 20 words): {20n mod 32}+[0,4) disjoint ->
//    conflict-free ldmatrix AND conflict-free STS with the (j2,n) decode below.
#define AW      216
#define BWH     40
#define SM_A    0
#define SM_B    (64 * AW * 2)             // 27648
#define SM_TOTAL (SM_B + 224 * BWH * 2)   // 45568

__device__ __forceinline__ void mma16816(float* d, const uint32_t* a, const uint32_t* b) {
    asm volatile(
        "mma.sync.aligned.m16n8k16.row.col.f32.f16.f16.f32 "
        "{%0,%1,%2,%3}, {%4,%5,%6,%7}, {%8,%9}, {%0,%1,%2,%3};"
        : "+f"(d[0]), "+f"(d[1]), "+f"(d[2]), "+f"(d[3])
        : "r"(a[0]), "r"(a[1]), "r"(a[2]), "r"(a[3]),
          "r"(b[0]), "r"(b[1]));
}
__device__ __forceinline__ void ldsm4(uint32_t* r, uint32_t addr) {
    asm volatile("ldmatrix.sync.aligned.m8n8.x4.shared.b16 {%0,%1,%2,%3}, [%4];"
        : "=r"(r[0]), "=r"(r[1]), "=r"(r[2]), "=r"(r[3]) : "r"(addr));
}
__device__ __forceinline__ void ldsm2(uint32_t* r, uint32_t addr) {
    asm volatile("ldmatrix.sync.aligned.m8n8.x2.shared.b16 {%0,%1}, [%2];"
        : "=r"(r[0]), "=r"(r[1]) : "r"(addr));
}

__device__ __forceinline__ uint32_t pack2h(float x, float y) {
    __half2 h = __floats2half2_rn(x, y);
    return *reinterpret_cast<uint32_t*>(&h);
}
__device__ __forceinline__ float swishf(float x) {
    return __fdividef(x, 1.0f + __expf(-x));
}
__device__ __forceinline__ float softplusf(float z) {
    return fmaxf(z, 0.0f) + log1pf(__expf(-fabsf(z)));
}
__device__ __forceinline__ float sig_transform(float x, float mx, float mn) {
    float t = (mx - softplusf(mx - 2.0f * x)) * 0.5f;
    t = (mn + softplusf(2.0f * t - mn)) * 0.5f;
    return __expf(t);
}

// ---- staging decode: pair index q -> (j2 = k-pair 0..15, n) ----
#define DECODE_QN(q, j2, n) do { j2 = ((q) >> 3) & 15; n = ((q) & 7) | (((q) >> 7) << 3); } while (0)

// ======== main staging: one 32-k chunk of W[krows x 200] -> pre (3584 pairs) ========
__device__ __forceinline__ void ldg_chunk(uint32_t* pre, const float* __restrict__ W,
                                          int krows, int c, int tid) {
#pragma unroll
    for (int p = 0; p < 14; ++p) {
        int q = p * NTH + tid, j2, n;
        DECODE_QN(q, j2, n);
        int j = c * 32 + 2 * j2;
        float w0 = 0.f, w1 = 0.f;
        if (n < HID) {
            if (j < krows)     w0 = __ldg(&W[(size_t)j * HID + n]);
            if (j + 1 < krows) w1 = __ldg(&W[(size_t)(j + 1) * HID + n]);
        }
        pre[p] = pack2h(w0, w1);
    }
}
__device__ __forceinline__ void sts_chunk(const uint32_t* pre, char* smc, int tid) {
#pragma unroll
    for (int p = 0; p < 14; ++p) {
        int q = p * NTH + tid, j2, n;
        DECODE_QN(q, j2, n);
        *(uint32_t*)(smc + SM_B + n * (BWH * 2) + j2 * 4) = pre[p];
    }
}

// ======== head staging: 32-k chunk of packed [mu(31)|pad|sig(31)|pad] ========
__device__ __forceinline__ void ldg_head(uint32_t* pre,
                                         const float* __restrict__ Wm,
                                         const float* __restrict__ Ws,
                                         int c, int tid) {
#pragma unroll
    for (int p = 0; p < 4; ++p) {
        int q = p * NTH + tid, j2, n;
        DECODE_QN(q, j2, n);               // q < 1024 -> n < 64
        int j = c * 32 + 2 * j2;
        float w0 = 0.f, w1 = 0.f;
        if (n < OUT_DIM) {
            if (j < HID)     w0 = __ldg(&Wm[(size_t)j * OUT_DIM + n]);
            if (j + 1 < HID) w1 = __ldg(&Wm[(size_t)(j + 1) * OUT_DIM + n]);
        } else if (n >= 32 && n < 32 + OUT_DIM) {
            int nn = n - 32;
            if (j < HID)     w0 = __ldg(&Ws[(size_t)j * OUT_DIM + nn]);
            if (j + 1 < HID) w1 = __ldg(&Ws[(size_t)(j + 1) * OUT_DIM + nn]);
        }
        pre[p] = pack2h(w0, w1);
    }
}
__device__ __forceinline__ void sts_head(const uint32_t* pre, char* smc, int tid) {
#pragma unroll
    for (int p = 0; p < 4; ++p) {
        int q = p * NTH + tid, j2, n;
        DECODE_QN(q, j2, n);
        *(uint32_t*)(smc + SM_B + n * (BWH * 2) + j2 * 4) = pre[p];
    }
}

__global__ __launch_bounds__(NTH, 2)
void ensemble_env_prob_hmma5(
    const float* __restrict__ s, const float* __restrict__ a,
    const float* __restrict__ W1, const float* __restrict__ b1,
    const float* __restrict__ Wh, const float* __restrict__ bh,
    const float* __restrict__ Wmu, const float* __restrict__ bmu,
    const float* __restrict__ Wsig, const float* __restrict__ bsig,
    const float* __restrict__ max_lv_s, const float* __restrict__ min_lv_s,
    const float* __restrict__ max_lv_r, const float* __restrict__ min_lv_r,
    float* __restrict__ out, int N)
{
    extern __shared__ char smc[];
    const uint32_t smb = (uint32_t)__cvta_generic_to_shared(smc);
    const int tid  = threadIdx.x;
    const int wid  = tid >> 5;
    const int lane = tid & 31;
    const int wm   = wid >> 2;         // 2 m-groups x 32 rows
    const int wn   = wid & 3;          // 4 n-groups x 56 cols (head: 16 cols)
    const int e    = blockIdx.y;
    const int n0   = blockIdx.x * TSAMP;

    // ldmatrix per-lane address components
    const int aRow0  = wm * 32 + (lane & 15);
    const int aColL  = (lane >> 4) * 8;
    const uint32_t aBase = smb + SM_A + aRow0 * (AW * 2);
    const int bRowL  = (lane & 7) + ((lane >> 4) << 3);
    const int bKoffL = ((lane >> 3) & 1) * 8;
    const uint32_t bBase = smb + SM_B + bRowL * (BWH * 2) + bKoffL * 2;

    // ---- zero A (covers all k padding)
    for (int i = tid; i < (64 * AW) / 2; i += NTH)
        ((uint32_t*)smc)[i] = 0u;
    __syncthreads();

    // ---- stage x = concat(s, a), fp16 into A
#pragma unroll
    for (int it = 0; it < 16; ++it) {
        int idx = it * NTH + tid;          // 4096 = 64 rows x 64 slots
        int m = idx >> 6, k = idx & 63;
        if (k < IN_DIM) {
            int n = n0 + m;
            float v = (k < S_DIM)
                    ? __ldg(&s[((size_t)n * ENS + e) * S_DIM + k])
                    : __ldg(&a[((size_t)n * ENS + e) * A_DIM + (k - S_DIM)]);
            *(uint16_t*)(smc + SM_A + m * (AW * 2) + k * 2) =
                __half_as_ushort(__float2half_rn(v));
        }
    }

    float acc[2][7][4];                    // [mf][nt][q]
    uint32_t pre[14];

    const float* Wm = Wmu  + (size_t)e * HID * OUT_DIM;
    const float* Ws = Wsig + (size_t)e * HID * OUT_DIM;

    // ================= layers 1..4 (swish epilogue back into A) =================
    ldg_chunk(pre, W1 + (size_t)e * IN_DIM * HID, IN_DIM, 0, tid);  // prefetch L0/C0
#pragma unroll 1
    for (int l = 0; l < 1 + NHID; ++l) {
        const float* W  = (l == 0) ? (W1 + (size_t)e * IN_DIM * HID)
                                   : (Wh + ((size_t)(l - 1) * ENS + e) * HID * HID);
        const float* bi = (l == 0) ? (b1 + (size_t)e * HID)
                                   : (bh + ((size_t)(l - 1) * ENS + e) * HID);
        const int krows = (l == 0) ? IN_DIM : HID;
        const int nks   = (l == 0) ? 3 : 13;   // 16-k steps
        const int nch   = (nks + 1) >> 1;      // 32-k chunks

#pragma unroll
        for (int mf = 0; mf < 2; ++mf)
#pragma unroll
            for (int nt = 0; nt < 7; ++nt)
#pragma unroll
                for (int q = 0; q < 4; ++q) acc[mf][nt][q] = 0.f;

#pragma unroll 1
        for (int c = 0; c < nch; ++c) {
            __syncthreads();                       // prev MMA done with B / A-epi done
            sts_chunk(pre, smc, tid);
            if (c + 1 < nch) {
                ldg_chunk(pre, W, krows, c + 1, tid);
            } else if (l < NHID) {
                // prefetch NEXT layer's chunk 0 — LDG latency hides behind
                // this chunk's MMA + the epilogue
                ldg_chunk(pre, Wh + ((size_t)l * ENS + e) * HID * HID, HID, 0, tid);
            } else {
                ldg_head(pre, Wm, Ws, 0, tid);     // prefetch head chunk 0
            }
            __syncthreads();                       // chunk visible
            const int nk = (nks - 2 * c > 2) ? 2 : (nks - 2 * c);
#pragma unroll
            for (int ks = 0; ks < 2; ++ks) {
                if (ks >= nk) break;
                const int kA = c * 32 + ks * 16 + aColL;
                uint32_t ah[2][4];
                ldsm4(ah[0], aBase + kA * 2);
                ldsm4(ah[1], aBase + 16 * (AW * 2) + kA * 2);
                const uint32_t bk = bBase + (ks * 16) * 2 + (wn * 56) * (BWH * 2);
#pragma unroll
                for (int ntp = 0; ntp < 3; ++ntp) {
                    uint32_t b4[4];
                    ldsm4(b4, bk + (ntp * 16) * (BWH * 2));
#pragma unroll
                    for (int mf = 0; mf < 2; ++mf) {
                        mma16816(acc[mf][2 * ntp],     ah[mf], b4);
                        mma16816(acc[mf][2 * ntp + 1], ah[mf], b4 + 2);
                    }
                }
                {
                    uint32_t b2[2];
                    ldsm2(b2, bk + 48 * (BWH * 2));
#pragma unroll
                    for (int mf = 0; mf < 2; ++mf)
                        mma16816(acc[mf][6], ah[mf], b2);
                }
            }
        }
        __syncthreads();                           // all A reads done before overwrite

        // ---- epilogue: +bias, swish, fp16, back into A (cols < 200)
        const int rr = wm * 32 + (lane >> 2);
#pragma unroll
        for (int nt = 0; nt < 7; ++nt) {
            int cc = wn * 56 + nt * 8 + (lane & 3) * 2;
            if (cc < HID) {
                float b0  = __ldg(&bi[cc]);
                float b1v = __ldg(&bi[cc + 1]);
#pragma unroll
                for (int mf = 0; mf < 2; ++mf) {
#pragma unroll
                    for (int rp = 0; rp < 2; ++rp) {
                        int row = rr + mf * 16 + rp * 8;
                        float h0 = swishf(acc[mf][nt][rp * 2]     + b0);
                        float h1 = swishf(acc[mf][nt][rp * 2 + 1] + b1v);
                        *(uint32_t*)(smc + SM_A + row * (AW * 2) + cc * 2) =
                            pack2h(h0, h1);
                    }
                }
            }
        }
    }

    // ================= head: packed [mu | sig], N = 64, warp covers 16 cols ========
#pragma unroll
    for (int mf = 0; mf < 2; ++mf)
#pragma unroll
        for (int nt = 0; nt < 2; ++nt)
#pragma unroll
            for (int q = 0; q < 4; ++q) acc[mf][nt][q] = 0.f;

    {
#pragma unroll 1
        for (int c = 0; c < 7; ++c) {
            __syncthreads();
            sts_head(pre, smc, tid);
            if (c + 1 < 7) ldg_head(pre, Wm, Ws, c + 1, tid);
            __syncthreads();
            const int nk = (13 - 2 * c > 2) ? 2 : (13 - 2 * c);
#pragma unroll
            for (int ks = 0; ks < 2; ++ks) {
                if (ks >= nk) break;
                const int kA = c * 32 + ks * 16 + aColL;
                uint32_t ah[2][4];
                ldsm4(ah[0], aBase + kA * 2);
                ldsm4(ah[1], aBase + 16 * (AW * 2) + kA * 2);
                uint32_t b4[4];
                ldsm4(b4, bBase + (ks * 16) * 2 + (wn * 16) * (BWH * 2));
#pragma unroll
                for (int mf = 0; mf < 2; ++mf) {
                    mma16816(acc[mf][0], ah[mf], b4);
                    mma16816(acc[mf][1], ah[mf], b4 + 2);
                }
            }
        }
    }

    // ================= head epilogue: direct global stores =================
    {
        const size_t NT_  = (size_t)N * ENS;
        const size_t NT30 = NT_ * 30, NT60 = NT_ * 60, NT61 = NT_ * 61;
        const bool  is_sig = (wn >= 2);
        const float* bo = (is_sig ? bsig : bmu) + (size_t)e * OUT_DIM;
        const int rr = wm * 32 + (lane >> 2);
#pragma unroll
        for (int mf = 0; mf < 2; ++mf) {
#pragma unroll
            for (int rp = 0; rp < 2; ++rp) {
                int row = rr + mf * 16 + rp * 8;
                size_t base = ((size_t)(n0 + row) * ENS + e);
#pragma unroll
                for (int nt = 0; nt < 2; ++nt) {
#pragma unroll
                    for (int i = 0; i < 2; ++i) {
                        int colg = wn * 16 + nt * 8 + (lane & 3) * 2 + i;  // 0..63
                        int col  = is_sig ? (colg - 32) : colg;            // 0..31
                        float v = acc[mf][nt][rp * 2 + i];
                        if (!is_sig) {
                            if (col < S_DIM)
                                out[base * S_DIM + col] = v + __ldg(&bo[col]);
                            else if (col == S_DIM)
                                out[NT60 + base] = v + __ldg(&bo[S_DIM]);
                        } else {
                            if (col < S_DIM) {
                                float x = v + __ldg(&bo[col]);
                                out[NT30 + base * S_DIM + col] =
                                    sig_transform(x, __ldg(&max_lv_s[col]),
                                                     __ldg(&min_lv_s[col]));
                            } else if (col == S_DIM) {
                                float x = v + __ldg(&bo[S_DIM]);
                                out[NT61 + base] =
                                    sig_transform(x, __ldg(&max_lv_r[0]),
                                                     __ldg(&min_lv_r[0]));
                            }
                        }
                    }
                }
            }
        }
    }
}

extern "C" void kernel_launch(void* const* d_in, const int* in_sizes, int n_in,
                              void* d_out, int out_size) {
    const float* s       = (const float*)d_in[0];
    const float* a       = (const float*)d_in[1];
    const float* W1      = (const float*)d_in[2];
    const float* b1      = (const float*)d_in[3];
    const float* Wh      = (const float*)d_in[4];
    const float* bh      = (const float*)d_in[5];
    const float* Wmu     = (const float*)d_in[6];
    const float* bmu     = (const float*)d_in[7];
    const float* Wsig    = (const float*)d_in[8];
    const float* bsig    = (const float*)d_in[9];
    const float* max_lvs = (const float*)d_in[10];
    const float* min_lvs = (const float*)d_in[11];
    const float* max_lvr = (const float*)d_in[12];
    const float* min_lvr = (const float*)d_in[13];
    float* out = (float*)d_out;

    const int N = in_sizes[0] / (ENS * S_DIM);   // 32768

    cudaFuncSetAttribute(ensemble_env_prob_hmma5,
                         cudaFuncAttributeMaxDynamicSharedMemorySize, SM_TOTAL);

    dim3 grid(N / TSAMP, ENS);                   // 512 x 7 = 3584 CTAs
    ensemble_env_prob_hmma5<<<grid, NTH, SM_TOTAL>>>(
        s, a, W1, b1, Wh, bh, Wmu, bmu, Wsig, bsig,
        max_lvs, min_lvs, max_lvr, min_lvr, out, N);
}

// round 14
// speedup vs baseline: 5.5442x; 1.5831x over previous
#include <cuda_runtime.h>
#include <cuda_fp16.h>
#include <cstdint>
#include <cstddef>

#define ENS     7
#define S_DIM   30
#define A_DIM   8
#define IN_DIM  38
#define HID     200
#define OUT_DIM 31
#define NHID    3
#define TSAMP   64
#define NTH     256

// ---- B chunk image: 224 rows x 40 halfs (row stride 20 words) ----
#define BWH     40
#define BIMG_W  4480                      // words per chunk image (224*20)
#define BIMG_B  (BIMG_W * 4)              // 17920 bytes
#define NCHUNKS 30                        // 2 (L0) + 3*7 (hidden) + 7 (head)

// ---- SMEM layout (bytes), per CTA = 81408 -> 2 CTAs/SM ----
#define AW      216
#define SM_A    0
#define SM_B0   (64 * AW * 2)             // 27648
#define SM_TOTAL (SM_B0 + 3 * BIMG_B)     // 81408

// ---- pre-packed weight images (global scratch; L2-resident, 3.76 MB) ----
__device__ __align__(16) uint32_t g_wimg[ENS * NCHUNKS * BIMG_W];

__device__ __forceinline__ const uint32_t* chunk_src(int e, int g) {
    return g_wimg + (size_t)(e * NCHUNKS + g) * BIMG_W;
}

__device__ __forceinline__ void mma16816(float* d, const uint32_t* a, const uint32_t* b) {
    asm volatile(
        "mma.sync.aligned.m16n8k16.row.col.f32.f16.f16.f32 "
        "{%0,%1,%2,%3}, {%4,%5,%6,%7}, {%8,%9}, {%0,%1,%2,%3};"
        : "+f"(d[0]), "+f"(d[1]), "+f"(d[2]), "+f"(d[3])
        : "r"(a[0]), "r"(a[1]), "r"(a[2]), "r"(a[3]),
          "r"(b[0]), "r"(b[1]));
}
__device__ __forceinline__ void ldsm4(uint32_t* r, uint32_t addr) {
    asm volatile("ldmatrix.sync.aligned.m8n8.x4.shared.b16 {%0,%1,%2,%3}, [%4];"
        : "=r"(r[0]), "=r"(r[1]), "=r"(r[2]), "=r"(r[3]) : "r"(addr));
}
__device__ __forceinline__ void ldsm2(uint32_t* r, uint32_t addr) {
    asm volatile("ldmatrix.sync.aligned.m8n8.x2.shared.b16 {%0,%1}, [%2];"
        : "=r"(r[0]), "=r"(r[1]) : "r"(addr));
}
__device__ __forceinline__ void cp16(uint32_t smem_dst, const void* gptr) {
    asm volatile("cp.async.cg.shared.global [%0], [%1], 16;\n"
        :: "r"(smem_dst), "l"(gptr));
}
#define CP_COMMIT() asm volatile("cp.async.commit_group;\n" ::: "memory")
#define CP_WAIT0()  asm volatile("cp.async.wait_group 0;\n" ::: "memory")
#define CP_WAIT1()  asm volatile("cp.async.wait_group 1;\n" ::: "memory")

__device__ __forceinline__ uint32_t pack2h(float x, float y) {
    __half2 h = __floats2half2_rn(x, y);
    return *reinterpret_cast<uint32_t*>(&h);
}
__device__ __forceinline__ float swishf(float x) {
    return __fdividef(x, 1.0f + __expf(-x));
}
__device__ __forceinline__ float softplusf(float z) {
    return fmaxf(z, 0.0f) + log1pf(__expf(-fabsf(z)));
}
__device__ __forceinline__ float sig_transform(float x, float mx, float mn) {
    float t = (mx - softplusf(mx - 2.0f * x)) * 0.5f;
    t = (mn + softplusf(2.0f * t - mn)) * 0.5f;
    return __expf(t);
}

// ================= prep: pack all weights into chunk images (once) =================
__global__ void prep_weights(const float* __restrict__ W1, const float* __restrict__ Wh,
                             const float* __restrict__ Wmu, const float* __restrict__ Wsig) {
    const int g = blockIdx.x, e = blockIdx.y, tid = threadIdx.x;
    uint32_t* dst = g_wimg + (size_t)(e * NCHUNKS + g) * BIMG_W;
    const float* W = nullptr; const float* W2 = nullptr;
    int krows = HID, c;
    bool head = false;
    if (g < 2)       { c = g;      W = W1 + (size_t)e * IN_DIM * HID; krows = IN_DIM; }
    else if (g < 23) { int t = g - 2; int l = t / 7; c = t % 7;
                       W = Wh + ((size_t)l * ENS + e) * HID * HID; }
    else             { head = true; c = g - 23;
                       W  = Wmu  + (size_t)e * HID * OUT_DIM;
                       W2 = Wsig + (size_t)e * HID * OUT_DIM; }
    for (int w = tid; w < BIMG_W; w += 256) {
        int n = w / 20, slot = w % 20;
        float w0 = 0.f, w1 = 0.f;
        if (slot < 16) {
            int j = c * 32 + 2 * slot;
            if (!head) {
                if (n < HID) {
                    if (j < krows)     w0 = __ldg(&W[(size_t)j * HID + n]);
                    if (j + 1 < krows) w1 = __ldg(&W[(size_t)(j + 1) * HID + n]);
                }
            } else {
                if (n < OUT_DIM) {
                    if (j < HID)     w0 = __ldg(&W[(size_t)j * OUT_DIM + n]);
                    if (j + 1 < HID) w1 = __ldg(&W[(size_t)(j + 1) * OUT_DIM + n]);
                } else if (n >= 32 && n < 32 + OUT_DIM) {
                    int nn = n - 32;
                    if (j < HID)     w0 = __ldg(&W2[(size_t)j * OUT_DIM + nn]);
                    if (j + 1 < HID) w1 = __ldg(&W2[(size_t)(j + 1) * OUT_DIM + nn]);
                }
            }
        }
        dst[w] = pack2h(w0, w1);
    }
}

// ---- stage one chunk image into a SMEM B buffer: 1120 x 16B cp.async ----
__device__ __forceinline__ void stage_async(uint32_t dst, const uint32_t* src, int tid) {
#pragma unroll
    for (int k = 0; k < 4; ++k) {
        int line = k * NTH + tid;
        cp16(dst + line * 16, src + line * 4);
    }
    if (tid < 96) {
        int line = 1024 + tid;
        cp16(dst + line * 16, src + line * 4);
    }
}

__global__ __launch_bounds__(NTH, 2)
void ensemble_env_prob_hmma6(
    const float* __restrict__ s, const float* __restrict__ a,
    const float* __restrict__ b1, const float* __restrict__ bh,
    const float* __restrict__ bmu, const float* __restrict__ bsig,
    const float* __restrict__ max_lv_s, const float* __restrict__ min_lv_s,
    const float* __restrict__ max_lv_r, const float* __restrict__ min_lv_r,
    float* __restrict__ out, int N)
{
    extern __shared__ char smc[];
    const uint32_t smb = (uint32_t)__cvta_generic_to_shared(smc);
    const int tid  = threadIdx.x;
    const int wid  = tid >> 5;
    const int lane = tid & 31;
    const int wm   = wid >> 2;         // 2 m-groups x 32 rows
    const int wn   = wid & 3;          // 4 n-groups x 56 cols (head: 16 cols)
    const int e    = blockIdx.y;
    const int n0   = blockIdx.x * TSAMP;

    const uint32_t bufB[3] = { smb + SM_B0, smb + SM_B0 + BIMG_B, smb + SM_B0 + 2 * BIMG_B };

    // ldmatrix per-lane address components
    const int aRow0  = wm * 32 + (lane & 15);
    const int aColL  = (lane >> 4) * 8;
    const uint32_t aBase = smb + SM_A + aRow0 * (AW * 2);
    const int bRowL  = (lane & 7) + ((lane >> 4) << 3);
    const int bKoffL = ((lane >> 3) & 1) * 8;
    const uint32_t bLane = bRowL * (BWH * 2) + bKoffL * 2;

    // kick off the weight pipeline immediately (chunks 0 and 1)
    stage_async(bufB[0], chunk_src(e, 0), tid); CP_COMMIT();
    stage_async(bufB[1], chunk_src(e, 1), tid); CP_COMMIT();

    // ---- zero A (covers all k padding)
    for (int i = tid; i < (64 * AW) / 2; i += NTH)
        ((uint32_t*)smc)[i] = 0u;
    __syncthreads();

    // ---- stage x = concat(s, a), fp16 into A
#pragma unroll
    for (int it = 0; it < 16; ++it) {
        int idx = it * NTH + tid;          // 4096 = 64 rows x 64 slots
        int m = idx >> 6, k = idx & 63;
        if (k < IN_DIM) {
            int n = n0 + m;
            float v = (k < S_DIM)
                    ? __ldg(&s[((size_t)n * ENS + e) * S_DIM + k])
                    : __ldg(&a[((size_t)n * ENS + e) * A_DIM + (k - S_DIM)]);
            *(uint16_t*)(smc + SM_A + m * (AW * 2) + k * 2) =
                __half_as_ushort(__float2half_rn(v));
        }
    }

    float acc[2][7][4];                    // [mf][nt][q]
    int g = 0;                             // global chunk counter

    // ================= layers 1..4 (swish epilogue back into A) =================
#pragma unroll 1
    for (int l = 0; l < 1 + NHID; ++l) {
        const float* bi = (l == 0) ? (b1 + (size_t)e * HID)
                                   : (bh + ((size_t)(l - 1) * ENS + e) * HID);
        const int nks = (l == 0) ? 3 : 13;
        const int nch = (nks + 1) >> 1;

#pragma unroll
        for (int mf = 0; mf < 2; ++mf)
#pragma unroll
            for (int nt = 0; nt < 7; ++nt)
#pragma unroll
                for (int q = 0; q < 4; ++q) acc[mf][nt][q] = 0.f;

#pragma unroll 1
        for (int c = 0; c < nch; ++c) {
            if (g == NCHUNKS - 1) { CP_WAIT0(); } else { CP_WAIT1(); }
            __syncthreads();                       // chunk g landed everywhere;
                                                   // all MMA/epilogue on bufB[(g+2)%3] done
            if (g + 2 < NCHUNKS) {
                stage_async(bufB[(g + 2) % 3], chunk_src(e, g + 2), tid);
                CP_COMMIT();
            }
            const uint32_t bB = bufB[g % 3] + bLane + (wn * 56) * (BWH * 2);
            const int nk = (nks - 2 * c > 2) ? 2 : (nks - 2 * c);
#pragma unroll
            for (int ks = 0; ks < 2; ++ks) {
                if (ks >= nk) break;
                const int kA = c * 32 + ks * 16 + aColL;
                uint32_t ah[2][4];
                ldsm4(ah[0], aBase + kA * 2);
                ldsm4(ah[1], aBase + 16 * (AW * 2) + kA * 2);
                const uint32_t bk = bB + (ks * 16) * 2;
#pragma unroll
                for (int ntp = 0; ntp < 3; ++ntp) {
                    uint32_t b4[4];
                    ldsm4(b4, bk + (ntp * 16) * (BWH * 2));
#pragma unroll
                    for (int mf = 0; mf < 2; ++mf) {
                        mma16816(acc[mf][2 * ntp],     ah[mf], b4);
                        mma16816(acc[mf][2 * ntp + 1], ah[mf], b4 + 2);
                    }
                }
                {
                    uint32_t b2[2];
                    ldsm2(b2, bk + 48 * (BWH * 2));
#pragma unroll
                    for (int mf = 0; mf < 2; ++mf)
                        mma16816(acc[mf][6], ah[mf], b2);
                }
            }
            ++g;
        }
        __syncthreads();                           // all A reads done before overwrite

        // ---- epilogue: +bias, swish, fp16, back into A (cols < 200)
        const int rr = wm * 32 + (lane >> 2);
#pragma unroll
        for (int nt = 0; nt < 7; ++nt) {
            int cc = wn * 56 + nt * 8 + (lane & 3) * 2;
            if (cc < HID) {
                float b0  = __ldg(&bi[cc]);
                float b1v = __ldg(&bi[cc + 1]);
#pragma unroll
                for (int mf = 0; mf < 2; ++mf) {
#pragma unroll
                    for (int rp = 0; rp < 2; ++rp) {
                        int row = rr + mf * 16 + rp * 8;
                        float h0 = swishf(acc[mf][nt][rp * 2]     + b0);
                        float h1 = swishf(acc[mf][nt][rp * 2 + 1] + b1v);
                        *(uint32_t*)(smc + SM_A + row * (AW * 2) + cc * 2) =
                            pack2h(h0, h1);
                    }
                }
            }
        }
    }

    // ================= head: packed [mu | sig], N = 64, warp covers 16 cols ========
#pragma unroll
    for (int mf = 0; mf < 2; ++mf)
#pragma unroll
        for (int nt = 0; nt < 2; ++nt)
#pragma unroll
            for (int q = 0; q < 4; ++q) acc[mf][nt][q] = 0.f;

#pragma unroll 1
    for (int c = 0; c < 7; ++c) {
        if (g == NCHUNKS - 1) { CP_WAIT0(); } else { CP_WAIT1(); }
        __syncthreads();
        if (g + 2 < NCHUNKS) {
            stage_async(bufB[(g + 2) % 3], chunk_src(e, g + 2), tid);
            CP_COMMIT();
        }
        const uint32_t bB = bufB[g % 3] + bLane + (wn * 16) * (BWH * 2);
        const int nk = (13 - 2 * c > 2) ? 2 : (13 - 2 * c);
#pragma unroll
        for (int ks = 0; ks < 2; ++ks) {
            if (ks >= nk) break;
            const int kA = c * 32 + ks * 16 + aColL;
            uint32_t ah[2][4];
            ldsm4(ah[0], aBase + kA * 2);
            ldsm4(ah[1], aBase + 16 * (AW * 2) + kA * 2);
            uint32_t b4[4];
            ldsm4(b4, bB + (ks * 16) * 2);
#pragma unroll
            for (int mf = 0; mf < 2; ++mf) {
                mma16816(acc[mf][0], ah[mf], b4);
                mma16816(acc[mf][1], ah[mf], b4 + 2);
            }
        }
        ++g;
    }

    // ================= head epilogue: direct global stores =================
    {
        const size_t NT_  = (size_t)N * ENS;
        const size_t NT30 = NT_ * 30, NT60 = NT_ * 60, NT61 = NT_ * 61;
        const bool  is_sig = (wn >= 2);
        const float* bo = (is_sig ? bsig : bmu) + (size_t)e * OUT_DIM;
        const int rr = wm * 32 + (lane >> 2);
#pragma unroll
        for (int mf = 0; mf < 2; ++mf) {
#pragma unroll
            for (int rp = 0; rp < 2; ++rp) {
                int row = rr + mf * 16 + rp * 8;
                size_t base = ((size_t)(n0 + row) * ENS + e);
#pragma unroll
                for (int nt = 0; nt < 2; ++nt) {
#pragma unroll
                    for (int i = 0; i < 2; ++i) {
                        int colg = wn * 16 + nt * 8 + (lane & 3) * 2 + i;  // 0..63
                        int col  = is_sig ? (colg - 32) : colg;            // 0..31
                        float v = acc[mf][nt][rp * 2 + i];
                        if (!is_sig) {
                            if (col < S_DIM)
                                out[base * S_DIM + col] = v + __ldg(&bo[col]);
                            else if (col == S_DIM)
                                out[NT60 + base] = v + __ldg(&bo[S_DIM]);
                        } else {
                            if (col < S_DIM) {
                                float x = v + __ldg(&bo[col]);
                                out[NT30 + base * S_DIM + col] =
                                    sig_transform(x, __ldg(&max_lv_s[col]),
                                                     __ldg(&min_lv_s[col]));
                            } else if (col == S_DIM) {
                                float x = v + __ldg(&bo[S_DIM]);
                                out[NT61 + base] =
                                    sig_transform(x, __ldg(&max_lv_r[0]),
                                                     __ldg(&min_lv_r[0]));
                            }
                        }
                    }
                }
            }
        }
    }
}

extern "C" void kernel_launch(void* const* d_in, const int* in_sizes, int n_in,
                              void* d_out, int out_size) {
    const float* s       = (const float*)d_in[0];
    const float* a       = (const float*)d_in[1];
    const float* W1      = (const float*)d_in[2];
    const float* b1      = (const float*)d_in[3];
    const float* Wh      = (const float*)d_in[4];
    const float* bh      = (const float*)d_in[5];
    const float* Wmu     = (const float*)d_in[6];
    const float* bmu     = (const float*)d_in[7];
    const float* Wsig    = (const float*)d_in[8];
    const float* bsig    = (const float*)d_in[9];
    const float* max_lvs = (const float*)d_in[10];
    const float* min_lvs = (const float*)d_in[11];
    const float* max_lvr = (const float*)d_in[12];
    const float* min_lvr = (const float*)d_in[13];
    float* out = (float*)d_out;

    const int N = in_sizes[0] / (ENS * S_DIM);   // 32768

    cudaFuncSetAttribute(ensemble_env_prob_hmma6,
                         cudaFuncAttributeMaxDynamicSharedMemorySize, SM_TOTAL);

    prep_weights<<<dim3(NCHUNKS, ENS), 256>>>(W1, Wh, Wmu, Wsig);

    dim3 grid(N / TSAMP, ENS);                   // 512 x 7 = 3584 CTAs
    ensemble_env_prob_hmma6<<<grid, NTH, SM_TOTAL>>>(
        s, a, b1, bh, bmu, bsig,
        max_lvs, min_lvs, max_lvr, min_lvr, out, N);
}